// round 7
// baseline (speedup 1.0000x reference)
#include <cuda_runtime.h>
#include <cuda_bf16.h>
#include <math.h>

typedef unsigned long long ull;
#define DEVI __device__ __forceinline__

// ---------------- packed f32x2 FFMA2 (sm_103a) ----------------
DEVI void fma2(ull& d, ull a, ull b) {
    asm("fma.rn.f32x2 %0, %1, %2, %0;" : "+l"(d) : "l"(a), "l"(b));
}
DEVI float psum(ull a) {
    float x, y;
    asm("mov.b64 {%0,%1}, %2;" : "=f"(x), "=f"(y) : "l"(a));
    return x + y;
}

// ---------------- activations (precise) ----------------
DEVI float sigm(float x)  { return 1.f / (1.f + expf(-x)); }
DEVI float siluf(float x) { return x / (1.f + expf(-x)); }
DEVI float softpl(float x){ return fmaxf(x, 0.f) + log1pf(expf(-fabsf(x))); }
DEVI float geluf(float x) { return 0.5f * x * (1.f + erff(x * 0.70710678f)); }

// ---------------- problem constants ----------------
#define NBLK 256
#define TB   32
#define NTHR 256

// output element offsets
#define SCAL_OFF 0ull
#define K_OFF    73728ull
#define KI_OFF   81920ull
#define ST0_OFF  90112ull
#define ST1_OFF  67198976ull

// smem layout (floats) — 113,792 B => 2 CTAs/SM
#define HS_OFF   0                          // hs  [32][132]
#define XS_OFF   (HS_OFF + 32*132)          // xss [32][260] (x tile stride 62 in input stage)
#define WS_OFF   (XS_OFF + 32*260)          // ws  [64][132] (w_in stride 62 in input stage)
#define TS_OFF   (WS_OFF + 64*132)          // ts  [32][132] pre-LN scratch / reduce buf
#define BC_OFF   (TS_OFF + 32*132)          // bcs [32][68]  B|C / gelu(t1) / out-GEMM reduce buf
#define DTB_OFF  (BC_OFF + 32*68)           // dtB [32][32]
#define YA_OFF   (DTB_OFF + 32*32)          // ya  [32]
#define SMEM_FLOATS (YA_OFF + 32)
#define SMEM_BYTES  (SMEM_FLOATS * 4)

// ---------------- cp.async slab load: 64 rows x 128 cols -> ws stride 132 ----
DEVI void cpa_slab(float* ws, const float* __restrict__ g, int gld) {
    #pragma unroll
    for (int t = 0; t < 8; t++) {
        int idx = threadIdx.x + t * NTHR;     // 0..2047
        int r = idx >> 5, kq = idx & 31;
        unsigned sa = (unsigned)__cvta_generic_to_shared(ws + r*132 + kq*4);
        const float* gp = g + r*gld + kq*4;
        asm volatile("cp.async.cg.shared.global [%0], [%1], 16;" :: "r"(sa), "l"(gp));
    }
    asm volatile("cp.async.commit_group;" ::: "memory");
}
DEVI void cpa_wait() { asm volatile("cp.async.wait_group 0;" ::: "memory"); }

// ---- 32x64 tile GEMM, half-K per warp (K=64 from kb). Warp tile 16x32,
// thread 4 rows x 4 cols. A: stride lda, W: stride 132. acc accumulates.
DEVI void gemmK(const float* __restrict__ a, int lda, const float* __restrict__ w,
                ull acc[4][4], int row0, int col0, int kb) {
    #pragma unroll 4
    for (int k = kb; k < kb + 64; k += 4) {
        ulonglong2 av[4], bv[4];
        #pragma unroll
        for (int i = 0; i < 4; i++) av[i] = *(const ulonglong2*)(a + (row0 + 4*i)*lda + k);
        #pragma unroll
        for (int j = 0; j < 4; j++) bv[j] = *(const ulonglong2*)(w + (col0 + 8*j)*132 + k);
        #pragma unroll
        for (int i = 0; i < 4; i++)
            #pragma unroll
            for (int j = 0; j < 4; j++) {
                fma2(acc[i][j], av[i].x, bv[j].x);
                fma2(acc[i][j], av[i].y, bv[j].y);
            }
    }
}

// same, with 4 streaming state stores per k-step (64 float4 per thread total)
DEVI void gemmKs(const float* __restrict__ a, int lda, const float* __restrict__ w,
                 ull acc[4][4], int row0, int col0, int kb,
                 const float* __restrict__ xrow, float4 db, float* __restrict__ p) {
    #pragma unroll 4
    for (int k = kb; k < kb + 64; k += 4) {
        ulonglong2 av[4], bv[4];
        #pragma unroll
        for (int i = 0; i < 4; i++) av[i] = *(const ulonglong2*)(a + (row0 + 4*i)*lda + k);
        #pragma unroll
        for (int j = 0; j < 4; j++) bv[j] = *(const ulonglong2*)(w + (col0 + 8*j)*132 + k);
        #pragma unroll
        for (int i = 0; i < 4; i++)
            #pragma unroll
            for (int j = 0; j < 4; j++) {
                fma2(acc[i][j], av[i].x, bv[j].x);
                fma2(acc[i][j], av[i].y, bv[j].y);
            }
        int d = k - kb;
        #pragma unroll
        for (int q = 0; q < 4; q++) {
            float xv = xrow[d + q];
            float4 v; v.x = xv*db.x; v.y = xv*db.y; v.z = xv*db.z; v.w = xv*db.w;
            __stcs((float4*)(p + (unsigned)(d + q)*32u), v);
        }
    }
}

// per-row LayerNorm over 128 cols; warp w owns rows [4w, 4w+4).
DEVI void do_ln(float* hs, const float* src, int lds,
                const float* __restrict__ g, const float* __restrict__ b, bool addres) {
    int w = threadIdx.x >> 5, lane = threadIdx.x & 31;
    float4 gg = *(const float4*)(g + lane*4);
    float4 bb = *(const float4*)(b + lane*4);
    for (int r = w*4; r < w*4 + 4; r++) {
        float4 v = *(const float4*)(src + r*lds + lane*4);
        if (addres) {
            float4 h = *(const float4*)(hs + r*132 + lane*4);
            v.x += h.x; v.y += h.y; v.z += h.z; v.w += h.w;
        }
        float s = v.x + v.y + v.z + v.w;
        float q = v.x*v.x + v.y*v.y + v.z*v.z + v.w*v.w;
        #pragma unroll
        for (int o = 16; o > 0; o >>= 1) {
            s += __shfl_xor_sync(0xffffffffu, s, o);
            q += __shfl_xor_sync(0xffffffffu, q, o);
        }
        float m   = s * (1.f/128.f);
        float inv = rsqrtf(fmaxf(q * (1.f/128.f) - m*m, 0.f) + 1e-5f);
        float4 o4;
        o4.x = (v.x - m)*inv*gg.x + bb.x;
        o4.y = (v.y - m)*inv*gg.y + bb.y;
        o4.z = (v.z - m)*inv*gg.z + bb.z;
        o4.w = (v.w - m)*inv*gg.w + bb.w;
        *(float4*)(hs + r*132 + lane*4) = o4;
    }
}

__global__ void __launch_bounds__(NTHR, 2) fused_kernel(
    const float* __restrict__ x,      const float* __restrict__ w_in,
    const float* __restrict__ b_in,   const float* __restrict__ ln_in_g,
    const float* __restrict__ ln_in_b,
    const float* __restrict__ in_w0,  const float* __restrict__ Dp0,
    const float* __restrict__ out_w0, const float* __restrict__ ln_g0,
    const float* __restrict__ ln_b0,
    const float* __restrict__ in_w1,  const float* __restrict__ Dp1,
    const float* __restrict__ out_w1, const float* __restrict__ ln_g1,
    const float* __restrict__ ln_b1,
    const float* __restrict__ fn_g,   const float* __restrict__ fn_b,
    const float* __restrict__ sh_w1,  const float* __restrict__ sh_b1,
    const float* __restrict__ sh_w2,  const float* __restrict__ sh_b2,
    const float* __restrict__ k_w,    const float* __restrict__ k_b,
    const float* __restrict__ ki_w,   const float* __restrict__ ki_b,
    float* __restrict__ outp)
{
    extern __shared__ float sm[];
    float* hs   = sm + HS_OFF;
    float* xss  = sm + XS_OFF;
    float* ws   = sm + WS_OFF;
    float* ts   = sm + TS_OFF;
    float* bcs  = sm + BC_OFF;
    float* dtBs = sm + DTB_OFF;
    float* yav  = sm + YA_OFF;

    const int tid  = threadIdx.x;
    const int wid  = tid >> 5, lane = tid & 31;
    const int wk   = wid & 1;                 // K half
    const int wr   = (wid >> 1) & 1;          // row half
    const int wcc  = wid >> 2;                // col half (32 cols each)
    const int lr   = lane >> 3, lc = lane & 7;
    const int row0 = wr*16 + lr;              // rows row0 + 4i
    const int col0 = wcc*32 + lc;             // cols col0 + 8j
    const int kb   = wk * 64;
    const int rowbase = blockIdx.x * TB;
    const int r_st = tid >> 3, sq_st = tid & 7;   // state-store mapping

    // ============ input stage: h = LN(x @ w_in^T + b_in) ============
    for (int idx = tid; idx < 32*58; idx += NTHR) {
        int r = idx / 58, k = idx - r*58;
        xss[r*62 + k] = x[(size_t)(rowbase + r)*58 + k];
    }
    for (int idx = tid; idx < 128*58; idx += NTHR) {
        int r = idx / 58, k = idx - r*58;
        ws[r*62 + k] = w_in[idx];
    }
    __syncthreads();
    {
        const int iwr = wid & 1, iwc = wid >> 1;      // warp grid 2x4 for 32x128 out
        const int ir0 = iwr*16 + lr;
        ull acc[4][4];
        #pragma unroll
        for (int i = 0; i < 4; i++)
            #pragma unroll
            for (int j = 0; j < 4; j++) acc[i][j] = 0ull;
        #pragma unroll 1
        for (int k = 0; k < 58; k += 2) {
            ull a[4], b[4];
            #pragma unroll
            for (int i = 0; i < 4; i++) a[i] = *(const ull*)(xss + (ir0 + 4*i)*62 + k);
            #pragma unroll
            for (int j = 0; j < 4; j++) b[j] = *(const ull*)(ws + (iwc*32 + lc + 8*j)*62 + k);
            #pragma unroll
            for (int i = 0; i < 4; i++)
                #pragma unroll
                for (int j = 0; j < 4; j++) fma2(acc[i][j], a[i], b[j]);
        }
        #pragma unroll
        for (int i = 0; i < 4; i++)
            #pragma unroll
            for (int j = 0; j < 4; j++) {
                int c = iwc*32 + lc + 8*j;
                ts[(ir0 + 4*i)*132 + c] = psum(acc[i][j]) + __ldg(b_in + c);
            }
    }
    __syncthreads();
    cpa_slab(ws, in_w0 + 512*128, 128);            // L0 B|C slab (overlaps LN)
    do_ln(hs, ts, 132, ln_in_g, ln_in_b, false);
    cpa_wait();
    __syncthreads();

    // ============ two mamba layers ============
    const float* in_w_l[2]  = {in_w0, in_w1};
    const float* Dp_l[2]    = {Dp0, Dp1};
    const float* out_w_l[2] = {out_w0, out_w1};
    const float* g_l[2]     = {ln_g0, ln_g1};
    const float* b_l[2]     = {ln_b0, ln_b1};
    const ull    soff_l[2]  = {ST0_OFF, ST1_OFF};

    for (int L = 0; L < 2; L++) {
        const float* in_w  = in_w_l[L];
        const float* Dp    = Dp_l[L];
        const float* out_w = out_w_l[L];
        const ull    soff  = soff_l[L];
        const float* nxt_after = (L == 0) ? (in_w1 + 512*128) : sh_w1;
        float* stb = outp + soff + ((ull)(rowbase + r_st)*256ull)*32ull + (ull)(sq_st*4);

        // ---- B|C chunk (proj cols 512..575) ----
        {
            ull acc[4][4];
            #pragma unroll
            for (int i = 0; i < 4; i++)
                #pragma unroll
                for (int j = 0; j < 4; j++) acc[i][j] = 0ull;
            gemmK(hs, 132, ws, acc, row0, col0, kb);
            if (wk == 0) {
                #pragma unroll
                for (int i = 0; i < 4; i++)
                    #pragma unroll
                    for (int j = 0; j < 4; j++)
                        ts[(row0 + 4*i)*132 + col0 + 8*j] = psum(acc[i][j]);
            }
            __syncthreads();
            cpa_slab(ws, in_w + 256*128, 128);     // xs0
            if (wk == 1) {
                #pragma unroll
                for (int i = 0; i < 4; i++)
                    #pragma unroll
                    for (int j = 0; j < 4; j++) {
                        int r = row0 + 4*i, c = col0 + 8*j;
                        bcs[r*68 + c] = ts[r*132 + c] + psum(acc[i][j]);
                    }
            }
            cpa_wait();
            __syncthreads();
        }

        // ---- per-row scalars: dt (col 576), bc = B·C, dtB, ya ----
        if (tid < 32) {
            const float* wdt = in_w + 576*128;
            float acc = 0.f;
            #pragma unroll 4
            for (int kk = 0; kk < 128; kk++) {
                int k = (kk + tid) & 127;
                acc += hs[tid*132 + k] * __ldg(wdt + k);
            }
            float dt = softpl(acc);
            float bc = 0.f;
            #pragma unroll
            for (int ss = 0; ss < 32; ss++) {
                int s = (ss + tid) & 31;
                float Bv = bcs[tid*68 + s];
                bc += Bv * bcs[tid*68 + 32 + s];
                dtBs[tid*32 + s] = dt * Bv;
            }
            yav[tid] = dt * bc;
        }

        // ---- x_ssm chunks (proj cols 256..511); sub>=1 interleaves store of sub-1 ----
        for (int sub = 0; sub < 4; sub++) {
            const float* nx = (sub < 3) ? (in_w + (256 + 64*(sub+1))*128) : in_w;
            ull acc[4][4];
            #pragma unroll
            for (int i = 0; i < 4; i++)
                #pragma unroll
                for (int j = 0; j < 4; j++) acc[i][j] = 0ull;
            if (sub == 0) {
                gemmK(hs, 132, ws, acc, row0, col0, kb);
            } else {
                float4 db = *(const float4*)(dtBs + r_st*32 + sq_st*4);
                gemmKs(hs, 132, ws, acc, row0, col0, kb,
                       xss + r_st*260 + (sub-1)*64, db, stb + (ull)((sub-1)*64)*32ull);
            }
            if (wk == 0) {
                #pragma unroll
                for (int i = 0; i < 4; i++)
                    #pragma unroll
                    for (int j = 0; j < 4; j++)
                        ts[(row0 + 4*i)*132 + col0 + 8*j] = psum(acc[i][j]);
            }
            __syncthreads();
            cpa_slab(ws, nx, 128);
            if (wk == 1) {
                #pragma unroll
                for (int i = 0; i < 4; i++)
                    #pragma unroll
                    for (int j = 0; j < 4; j++) {
                        int r = row0 + 4*i, c = col0 + 8*j;
                        float fin = ts[r*132 + c] + psum(acc[i][j]);
                        xss[r*260 + sub*64 + c] = siluf(fin);
                    }
            }
            cpa_wait();
            __syncthreads();
        }

        // ---- z chunks (proj cols 0..255); z0 interleaves store of xs3 ----
        for (int sub = 0; sub < 4; sub++) {
            const float* nx; int ngld;
            if (sub < 3) { nx = in_w + 64*(sub+1)*128; ngld = 128; }
            else         { nx = out_w;                 ngld = 256; }
            ull acc[4][4];
            #pragma unroll
            for (int i = 0; i < 4; i++)
                #pragma unroll
                for (int j = 0; j < 4; j++) acc[i][j] = 0ull;
            if (sub == 0) {
                float4 db = *(const float4*)(dtBs + r_st*32 + sq_st*4);
                gemmKs(hs, 132, ws, acc, row0, col0, kb,
                       xss + r_st*260 + 192, db, stb + (ull)192*32ull);
            } else {
                gemmK(hs, 132, ws, acc, row0, col0, kb);
            }
            if (wk == 0) {
                #pragma unroll
                for (int i = 0; i < 4; i++)
                    #pragma unroll
                    for (int j = 0; j < 4; j++)
                        ts[(row0 + 4*i)*132 + col0 + 8*j] = psum(acc[i][j]);
            }
            __syncthreads();
            cpa_slab(ws, nx, ngld);
            if (wk == 1) {
                #pragma unroll
                for (int i = 0; i < 4; i++)
                    #pragma unroll
                    for (int j = 0; j < 4; j++) {
                        int r = row0 + 4*i, c = col0 + 8*j;
                        float fin = ts[r*132 + c] + psum(acc[i][j]);
                        float xv = xss[r*260 + sub*64 + c];
                        xss[r*260 + sub*64 + c] = siluf(fin) * xv * (yav[r] + __ldg(Dp + sub*64 + c));
                    }
            }
            cpa_wait();
            __syncthreads();
        }

        // ---- out GEMM: ts = u @ out_w^T (128 cols, K=256, 2x2 slabs) ----
        for (int ch = 0; ch < 2; ch++) {
            ull acc[4][4];
            #pragma unroll
            for (int i = 0; i < 4; i++)
                #pragma unroll
                for (int j = 0; j < 4; j++) acc[i][j] = 0ull;
            gemmK(xss, 260, ws, acc, row0, col0, kb);              // kh=0
            __syncthreads();
            cpa_slab(ws, out_w + (size_t)ch*64*256 + 128, 256);    // kh=1 slab
            cpa_wait();
            __syncthreads();
            gemmK(xss + 128, 260, ws, acc, row0, col0, kb);        // kh=1
            if (wk == 0) {
                #pragma unroll
                for (int i = 0; i < 4; i++)
                    #pragma unroll
                    for (int j = 0; j < 4; j++)
                        bcs[(row0 + 4*i)*68 + col0 + 8*j] = psum(acc[i][j]);
            }
            __syncthreads();
            {
                const float* nx = (ch == 0) ? (out_w + 64*256) : nxt_after;
                cpa_slab(ws, nx, (ch == 0) ? 256 : 128);
            }
            if (wk == 1) {
                #pragma unroll
                for (int i = 0; i < 4; i++)
                    #pragma unroll
                    for (int j = 0; j < 4; j++) {
                        int r = row0 + 4*i, c = col0 + 8*j;
                        ts[r*132 + ch*64 + c] = bcs[r*68 + c] + psum(acc[i][j]);
                    }
            }
            cpa_wait();
            __syncthreads();
        }
        do_ln(hs, ts, 132, g_l[L], b_l[L], true);   // h = LN(h + out)
        __syncthreads();
    }

    // ============ final LN + heads ============
    do_ln(hs, hs, 132, fn_g, fn_b, false);
    __syncthreads();

    // t1 = gelu(h @ sh_w1^T + sh_b1) -> bcs (stride 68); sh_w1 already in ws
    {
        ull acc[4][4];
        #pragma unroll
        for (int i = 0; i < 4; i++)
            #pragma unroll
            for (int j = 0; j < 4; j++) acc[i][j] = 0ull;
        gemmK(hs, 132, ws, acc, row0, col0, kb);
        if (wk == 0) {
            #pragma unroll
            for (int i = 0; i < 4; i++)
                #pragma unroll
                for (int j = 0; j < 4; j++)
                    ts[(row0 + 4*i)*132 + col0 + 8*j] = psum(acc[i][j]);
        }
        __syncthreads();
        if (wk == 1) {
            #pragma unroll
            for (int i = 0; i < 4; i++)
                #pragma unroll
                for (int j = 0; j < 4; j++) {
                    int r = row0 + 4*i, c = col0 + 8*j;
                    float fin = ts[r*132 + c] + psum(acc[i][j]);
                    bcs[r*68 + c] = geluf(fin + __ldg(sh_b1 + c));
                }
        }
        __syncthreads();
    }

    // scaling = softplus(t1 @ sh_w2^T + sh_b2)  (9 cols)
    for (int idx = tid; idx < 32*9; idx += NTHR) {
        int r = idx / 9, c = idx - r*9;
        float acc = __ldg(sh_b2 + c);
        #pragma unroll 4
        for (int ss = 0; ss < 64; ss++) {
            int s = (ss + tid) & 63;
            acc += bcs[r*68 + s] * __ldg(sh_w2 + c*64 + s);
        }
        outp[SCAL_OFF + (ull)(rowbase + r)*9ull + c] = softpl(acc);
    }

    // K, K_internal (per-row dots over h)
    if (tid < 32) {
        float a0 = 0.f, a1 = 0.f;
        #pragma unroll 4
        for (int kk = 0; kk < 128; kk++) {
            int k = (kk + tid) & 127;
            float hv = hs[tid*132 + k];
            a0 += hv * __ldg(k_w + k);
            a1 += hv * __ldg(ki_w + k);
        }
        outp[K_OFF  + (ull)(rowbase + tid)] = sigm(a0 + __ldg(k_b));
        outp[KI_OFF + (ull)(rowbase + tid)] = sigm(a1 + __ldg(ki_b));
    }
}

extern "C" void kernel_launch(void* const* d_in, const int* in_sizes, int n_in,
                              void* d_out, int out_size) {
    (void)in_sizes; (void)n_in; (void)out_size;
    cudaFuncSetAttribute(fused_kernel, cudaFuncAttributeMaxDynamicSharedMemorySize, SMEM_BYTES);
    fused_kernel<<<NBLK, NTHR, SMEM_BYTES>>>(
        (const float*)d_in[0],  (const float*)d_in[1],  (const float*)d_in[2],
        (const float*)d_in[3],  (const float*)d_in[4],
        (const float*)d_in[5],  (const float*)d_in[7],  (const float*)d_in[8],
        (const float*)d_in[9],  (const float*)d_in[10],
        (const float*)d_in[11], (const float*)d_in[13], (const float*)d_in[14],
        (const float*)d_in[15], (const float*)d_in[16],
        (const float*)d_in[17], (const float*)d_in[18],
        (const float*)d_in[19], (const float*)d_in[20],
        (const float*)d_in[21], (const float*)d_in[22],
        (const float*)d_in[23], (const float*)d_in[24],
        (const float*)d_in[25], (const float*)d_in[26],
        (float*)d_out);
}

// round 8
// speedup vs baseline: 1.0640x; 1.0640x over previous
#include <cuda_runtime.h>
#include <cuda_bf16.h>
#include <math.h>

typedef unsigned long long ull;
#define DEVI __device__ __forceinline__

// ---------------- packed f32x2 FFMA2 (sm_103a) ----------------
DEVI void fma2(ull& d, ull a, ull b) {
    asm("fma.rn.f32x2 %0, %1, %2, %0;" : "+l"(d) : "l"(a), "l"(b));
}
DEVI float psum(ull a) {
    float x, y;
    asm("mov.b64 {%0,%1}, %2;" : "=f"(x), "=f"(y) : "l"(a));
    return x + y;
}

// ---------------- activations (precise) ----------------
DEVI float sigm(float x)  { return 1.f / (1.f + expf(-x)); }
DEVI float siluf(float x) { return x / (1.f + expf(-x)); }
DEVI float softpl(float x){ return fmaxf(x, 0.f) + log1pf(expf(-fabsf(x))); }
DEVI float geluf(float x) { return 0.5f * x * (1.f + erff(x * 0.70710678f)); }

// ---------------- problem constants ----------------
#define NBLK 256
#define TB   32
#define NTHR 256

// output element offsets
#define SCAL_OFF 0ull
#define K_OFF    73728ull
#define KI_OFF   81920ull
#define ST0_OFF  90112ull
#define ST1_OFF  67198976ull

// smem layout (floats) — 113,792 B => 2 CTAs/SM
#define HS_OFF   0                          // hs  [32][132]
#define XS_OFF   (HS_OFF + 32*132)          // xss [32][260] (x tile stride 62 in input stage)
#define WS_OFF   (XS_OFF + 32*260)          // ws  [64][132] (w_in stride 62 in input stage)
#define TS_OFF   (WS_OFF + 64*132)          // ts  [32][132] pre-LN scratch
#define BC_OFF   (TS_OFF + 32*132)          // bcs [32][68]
#define DTB_OFF  (BC_OFF + 32*68)           // dtB [32][32]
#define YA_OFF   (DTB_OFF + 32*32)          // ya  [32]
#define SMEM_FLOATS (YA_OFF + 32)
#define SMEM_BYTES  (SMEM_FLOATS * 4)

// ---------------- cp.async slab load: 64 rows x 128 cols -> ws stride 132 ----
DEVI void cpa_slab(float* ws, const float* __restrict__ g, int gld) {
    #pragma unroll
    for (int t = 0; t < 8; t++) {
        int idx = threadIdx.x + t * NTHR;     // 0..2047
        int r = idx >> 5, kq = idx & 31;
        unsigned sa = (unsigned)__cvta_generic_to_shared(ws + r*132 + kq*4);
        const float* gp = g + r*gld + kq*4;
        asm volatile("cp.async.cg.shared.global [%0], [%1], 16;" :: "r"(sa), "l"(gp));
    }
    asm volatile("cp.async.commit_group;" ::: "memory");
}
DEVI void cpa_wait() { asm volatile("cp.async.wait_group 0;" ::: "memory"); }

// ---- 32x64 tile GEMM, full K=128. Warp tile 16x16; thread 4 rows x 2 cols.
DEVI void gemm32(const float* __restrict__ a, int lda, const float* __restrict__ w,
                 float vals[4][2], int row0, int col0) {
    ull acc[4][2];
    #pragma unroll
    for (int i = 0; i < 4; i++)
        #pragma unroll
        for (int j = 0; j < 2; j++) acc[i][j] = 0ull;
    #pragma unroll 4
    for (int k = 0; k < 128; k += 4) {
        ulonglong2 av[4], bv[2];
        #pragma unroll
        for (int i = 0; i < 4; i++) av[i] = *(const ulonglong2*)(a + (row0 + 4*i)*lda + k);
        #pragma unroll
        for (int j = 0; j < 2; j++) bv[j] = *(const ulonglong2*)(w + (col0 + 8*j)*132 + k);
        #pragma unroll
        for (int i = 0; i < 4; i++)
            #pragma unroll
            for (int j = 0; j < 2; j++) {
                fma2(acc[i][j], av[i].x, bv[j].x);
                fma2(acc[i][j], av[i].y, bv[j].y);
            }
    }
    #pragma unroll
    for (int i = 0; i < 4; i++)
        #pragma unroll
        for (int j = 0; j < 2; j++) vals[i][j] += psum(acc[i][j]);
}

// same, with NS streaming state stores per k-step (NS*32 float4 per thread).
// xrow: silu(x_ssm) slice base (smem, broadcast). p: coalesced .cs float4 base.
template<int NS>
DEVI void gemm32st(const float* __restrict__ a, int lda, const float* __restrict__ w,
                   float vals[4][2], int row0, int col0,
                   const float* __restrict__ xrow, float4 db, float* __restrict__ p) {
    ull acc[4][2];
    #pragma unroll
    for (int i = 0; i < 4; i++)
        #pragma unroll
        for (int j = 0; j < 2; j++) acc[i][j] = 0ull;
    #pragma unroll 4
    for (int k = 0; k < 128; k += 4) {
        ulonglong2 av[4], bv[2];
        #pragma unroll
        for (int i = 0; i < 4; i++) av[i] = *(const ulonglong2*)(a + (row0 + 4*i)*lda + k);
        #pragma unroll
        for (int j = 0; j < 2; j++) bv[j] = *(const ulonglong2*)(w + (col0 + 8*j)*132 + k);
        #pragma unroll
        for (int i = 0; i < 4; i++)
            #pragma unroll
            for (int j = 0; j < 2; j++) {
                fma2(acc[i][j], av[i].x, bv[j].x);
                fma2(acc[i][j], av[i].y, bv[j].y);
            }
        int t = k >> 2;                            // 0..31
        {
            float xv = xrow[t];
            float4 v; v.x = xv*db.x; v.y = xv*db.y; v.z = xv*db.z; v.w = xv*db.w;
            __stcs((float4*)(p + (unsigned)t*32u), v);
        }
        if (NS == 2) {
            float xv = xrow[t + 32];
            float4 v; v.x = xv*db.x; v.y = xv*db.y; v.z = xv*db.z; v.w = xv*db.w;
            __stcs((float4*)(p + (unsigned)(t + 32)*32u), v);
        }
    }
    #pragma unroll
    for (int i = 0; i < 4; i++)
        #pragma unroll
        for (int j = 0; j < 2; j++) vals[i][j] += psum(acc[i][j]);
}

// per-row LayerNorm over 128 cols; warp w owns rows [4w, 4w+4).
DEVI void do_ln(float* hs, const float* src, int lds,
                const float* __restrict__ g, const float* __restrict__ b, bool addres) {
    int w = threadIdx.x >> 5, lane = threadIdx.x & 31;
    float4 gg = *(const float4*)(g + lane*4);
    float4 bb = *(const float4*)(b + lane*4);
    for (int r = w*4; r < w*4 + 4; r++) {
        float4 v = *(const float4*)(src + r*lds + lane*4);
        if (addres) {
            float4 h = *(const float4*)(hs + r*132 + lane*4);
            v.x += h.x; v.y += h.y; v.z += h.z; v.w += h.w;
        }
        float s = v.x + v.y + v.z + v.w;
        float q = v.x*v.x + v.y*v.y + v.z*v.z + v.w*v.w;
        #pragma unroll
        for (int o = 16; o > 0; o >>= 1) {
            s += __shfl_xor_sync(0xffffffffu, s, o);
            q += __shfl_xor_sync(0xffffffffu, q, o);
        }
        float m   = s * (1.f/128.f);
        float inv = rsqrtf(fmaxf(q * (1.f/128.f) - m*m, 0.f) + 1e-5f);
        float4 o4;
        o4.x = (v.x - m)*inv*gg.x + bb.x;
        o4.y = (v.y - m)*inv*gg.y + bb.y;
        o4.z = (v.z - m)*inv*gg.z + bb.z;
        o4.w = (v.w - m)*inv*gg.w + bb.w;
        *(float4*)(hs + r*132 + lane*4) = o4;
    }
}

__global__ void __launch_bounds__(NTHR, 2) fused_kernel(
    const float* __restrict__ x,      const float* __restrict__ w_in,
    const float* __restrict__ b_in,   const float* __restrict__ ln_in_g,
    const float* __restrict__ ln_in_b,
    const float* __restrict__ in_w0,  const float* __restrict__ Dp0,
    const float* __restrict__ out_w0, const float* __restrict__ ln_g0,
    const float* __restrict__ ln_b0,
    const float* __restrict__ in_w1,  const float* __restrict__ Dp1,
    const float* __restrict__ out_w1, const float* __restrict__ ln_g1,
    const float* __restrict__ ln_b1,
    const float* __restrict__ fn_g,   const float* __restrict__ fn_b,
    const float* __restrict__ sh_w1,  const float* __restrict__ sh_b1,
    const float* __restrict__ sh_w2,  const float* __restrict__ sh_b2,
    const float* __restrict__ k_w,    const float* __restrict__ k_b,
    const float* __restrict__ ki_w,   const float* __restrict__ ki_b,
    float* __restrict__ outp)
{
    extern __shared__ float sm[];
    float* hs   = sm + HS_OFF;
    float* xss  = sm + XS_OFF;
    float* ws   = sm + WS_OFF;
    float* ts   = sm + TS_OFF;
    float* bcs  = sm + BC_OFF;
    float* dtBs = sm + DTB_OFF;
    float* yav  = sm + YA_OFF;

    const int tid  = threadIdx.x;
    const int wid  = tid >> 5, lane = tid & 31;
    const int wr   = wid & 1,  wc2  = wid >> 1;      // warp grid 2x4
    const int lr   = lane >> 3, lc  = lane & 7;      // lane grid 4x8
    const int row0 = wr*16 + lr;
    const int col0 = wc2*16 + lc;
    const int rowbase = blockIdx.x * TB;
    const int r_st = tid >> 3, sq_st = tid & 7;      // state-store mapping

    // ============ input stage: h = LN(x @ w_in^T + b_in) ============
    for (int idx = tid; idx < 32*58; idx += NTHR) {
        int r = idx / 58, k = idx - r*58;
        xss[r*62 + k] = x[(size_t)(rowbase + r)*58 + k];
    }
    for (int idx = tid; idx < 128*58; idx += NTHR) {
        int r = idx / 58, k = idx - r*58;
        ws[r*62 + k] = w_in[idx];
    }
    __syncthreads();
    {
        ull acc[4][4];
        #pragma unroll
        for (int i = 0; i < 4; i++)
            #pragma unroll
            for (int j = 0; j < 4; j++) acc[i][j] = 0ull;
        #pragma unroll 1
        for (int k = 0; k < 58; k += 2) {
            ull a[4], b[4];
            #pragma unroll
            for (int i = 0; i < 4; i++) a[i] = *(const ull*)(xss + (row0 + 4*i)*62 + k);
            #pragma unroll
            for (int j = 0; j < 4; j++) b[j] = *(const ull*)(ws + (wc2*32 + lc + 8*j)*62 + k);
            #pragma unroll
            for (int i = 0; i < 4; i++)
                #pragma unroll
                for (int j = 0; j < 4; j++) fma2(acc[i][j], a[i], b[j]);
        }
        #pragma unroll
        for (int i = 0; i < 4; i++)
            #pragma unroll
            for (int j = 0; j < 4; j++) {
                int c = wc2*32 + lc + 8*j;
                ts[(row0 + 4*i)*132 + c] = psum(acc[i][j]) + __ldg(b_in + c);
            }
    }
    __syncthreads();
    cpa_slab(ws, in_w0 + 512*128, 128);            // L0 B|C slab; LN covers latency
    do_ln(hs, ts, 132, ln_in_g, ln_in_b, false);
    cpa_wait();
    __syncthreads();

    // ============ two mamba layers ============
    const float* in_w_l[2]  = {in_w0, in_w1};
    const float* Dp_l[2]    = {Dp0, Dp1};
    const float* out_w_l[2] = {out_w0, out_w1};
    const float* g_l[2]     = {ln_g0, ln_g1};
    const float* b_l[2]     = {ln_b0, ln_b1};
    const ull    soff_l[2]  = {ST0_OFF, ST1_OFF};

    for (int L = 0; L < 2; L++) {
        const float* in_w  = in_w_l[L];
        const float* Dp    = Dp_l[L];
        const float* out_w = out_w_l[L];
        const ull    soff  = soff_l[L];
        const float* nxt_after = (L == 0) ? (in_w1 + 512*128) : sh_w1;
        float* stb = outp + soff + ((ull)(rowbase + r_st)*256ull)*32ull + (ull)(sq_st*4);
        const float* xrb = xss + r_st*260;

        // ---- B|C chunk (proj cols 512..575) ----
        {
            float vals[4][2] = {};
            gemm32(hs, 132, ws, vals, row0, col0);
            __syncthreads();                       // ws free
            cpa_slab(ws, in_w + 256*128, 128);     // xs0
            #pragma unroll
            for (int i = 0; i < 4; i++)
                #pragma unroll
                for (int j = 0; j < 2; j++)
                    bcs[(row0 + 4*i)*68 + col0 + 8*j] = vals[i][j];
            cpa_wait();
            __syncthreads();
        }

        // ---- per-row scalars: dt (col 576), bc = B·C, dtB, ya ----
        // (warp 0 only; other warps proceed into xs0 — consumers of dtB/ya
        //  are beyond the xs0-end barrier, so visibility is guaranteed)
        if (tid < 32) {
            const float* wdt = in_w + 576*128;
            float acc = 0.f;
            #pragma unroll 4
            for (int kk = 0; kk < 128; kk++) {
                int k = (kk + tid) & 127;
                acc += hs[tid*132 + k] * __ldg(wdt + k);
            }
            float dt = softpl(acc);
            float bc = 0.f;
            #pragma unroll
            for (int ss = 0; ss < 32; ss++) {
                int s = (ss + tid) & 31;
                float Bv = bcs[tid*68 + s];
                bc += Bv * bcs[tid*68 + 32 + s];
                dtBs[tid*32 + s] = dt * Bv;
            }
            yav[tid] = dt * bc;
        }

        // ---- x_ssm chunks (proj cols 256..511) ----
        // store schedule (race-free): xs1<-xs0[0:32], xs2<-xs0[32:64],
        // xs3<-xs1[0:64], z0<-xs2[0:64], z1<-xs3[0:32], z2<-xs3[32:64]
        for (int sub = 0; sub < 4; sub++) {
            const float* nx = (sub < 3) ? (in_w + (256 + 64*(sub+1))*128) : in_w;
            float vals[4][2] = {};
            float4 db = *(const float4*)(dtBs + r_st*32 + sq_st*4); // valid for sub>=1
            if (sub == 0)      gemm32(hs, 132, ws, vals, row0, col0);
            else if (sub == 1) gemm32st<1>(hs, 132, ws, vals, row0, col0, xrb + 0,   db, stb + 0u);
            else if (sub == 2) gemm32st<1>(hs, 132, ws, vals, row0, col0, xrb + 32,  db, stb + 32u*32u);
            else               gemm32st<2>(hs, 132, ws, vals, row0, col0, xrb + 64,  db, stb + 64u*32u);
            __syncthreads();
            cpa_slab(ws, nx, 128);
            #pragma unroll
            for (int i = 0; i < 4; i++)
                #pragma unroll
                for (int j = 0; j < 2; j++)
                    xss[(row0 + 4*i)*260 + sub*64 + col0 + 8*j] = siluf(vals[i][j]);
            cpa_wait();
            __syncthreads();
        }

        // ---- z chunks (proj cols 0..255) ----
        for (int sub = 0; sub < 4; sub++) {
            const float* nx; int ngld;
            if (sub < 3) { nx = in_w + 64*(sub+1)*128; ngld = 128; }
            else         { nx = out_w;                 ngld = 256; }
            float vals[4][2] = {};
            float4 db = *(const float4*)(dtBs + r_st*32 + sq_st*4);
            if (sub == 0)      gemm32st<2>(hs, 132, ws, vals, row0, col0, xrb + 128, db, stb + 128u*32u);
            else if (sub == 1) gemm32st<1>(hs, 132, ws, vals, row0, col0, xrb + 192, db, stb + 192u*32u);
            else if (sub == 2) gemm32st<1>(hs, 132, ws, vals, row0, col0, xrb + 224, db, stb + 224u*32u);
            else               gemm32(hs, 132, ws, vals, row0, col0);
            __syncthreads();
            cpa_slab(ws, nx, ngld);
            #pragma unroll
            for (int i = 0; i < 4; i++)
                #pragma unroll
                for (int j = 0; j < 2; j++) {
                    int r = row0 + 4*i, c = sub*64 + col0 + 8*j;
                    float xv = xss[r*260 + c];
                    xss[r*260 + c] = siluf(vals[i][j]) * xv * (yav[r] + __ldg(Dp + c));
                }
            cpa_wait();
            __syncthreads();
        }

        // ---- out GEMM: ts = u @ out_w^T (128 cols, K=256, 2x2 slabs) ----
        for (int ch = 0; ch < 2; ch++) {
            float vals[4][2] = {};
            gemm32(xss, 260, ws, vals, row0, col0);                // kh0
            __syncthreads();
            cpa_slab(ws, out_w + (size_t)ch*64*256 + 128, 256);    // kh1 slab
            cpa_wait();
            __syncthreads();
            gemm32(xss + 128, 260, ws, vals, row0, col0);          // kh1
            __syncthreads();
            {
                const float* nx = (ch == 0) ? (out_w + 64*256) : nxt_after;
                cpa_slab(ws, nx, (ch == 0) ? 256 : 128);
            }
            #pragma unroll
            for (int i = 0; i < 4; i++)
                #pragma unroll
                for (int j = 0; j < 2; j++)
                    ts[(row0 + 4*i)*132 + ch*64 + col0 + 8*j] = vals[i][j];
            cpa_wait();
            __syncthreads();
        }
        do_ln(hs, ts, 132, g_l[L], b_l[L], true);   // h = LN(h + out)
        __syncthreads();
    }

    // ============ final LN + heads ============
    do_ln(hs, hs, 132, fn_g, fn_b, false);
    __syncthreads();

    // t1 = gelu(h @ sh_w1^T + sh_b1) -> bcs (stride 68); sh_w1 already in ws
    {
        float vals[4][2] = {};
        gemm32(hs, 132, ws, vals, row0, col0);
        #pragma unroll
        for (int i = 0; i < 4; i++)
            #pragma unroll
            for (int j = 0; j < 2; j++) {
                int c = col0 + 8*j;
                bcs[(row0 + 4*i)*68 + c] = geluf(vals[i][j] + __ldg(sh_b1 + c));
            }
    }
    __syncthreads();

    // scaling = softplus(t1 @ sh_w2^T + sh_b2)  (9 cols)
    for (int idx = tid; idx < 32*9; idx += NTHR) {
        int r = idx / 9, c = idx - r*9;
        float acc = __ldg(sh_b2 + c);
        #pragma unroll 4
        for (int ss = 0; ss < 64; ss++) {
            int s = (ss + tid) & 63;
            acc += bcs[r*68 + s] * __ldg(sh_w2 + c*64 + s);
        }
        outp[SCAL_OFF + (ull)(rowbase + r)*9ull + c] = softpl(acc);
    }

    // K, K_internal (per-row dots over h)
    if (tid < 32) {
        float a0 = 0.f, a1 = 0.f;
        #pragma unroll 4
        for (int kk = 0; kk < 128; kk++) {
            int k = (kk + tid) & 127;
            float hv = hs[tid*132 + k];
            a0 += hv * __ldg(k_w + k);
            a1 += hv * __ldg(ki_w + k);
        }
        outp[K_OFF  + (ull)(rowbase + tid)] = sigm(a0 + __ldg(k_b));
        outp[KI_OFF + (ull)(rowbase + tid)] = sigm(a1 + __ldg(ki_b));
    }
}

extern "C" void kernel_launch(void* const* d_in, const int* in_sizes, int n_in,
                              void* d_out, int out_size) {
    (void)in_sizes; (void)n_in; (void)out_size;
    cudaFuncSetAttribute(fused_kernel, cudaFuncAttributeMaxDynamicSharedMemorySize, SMEM_BYTES);
    fused_kernel<<<NBLK, NTHR, SMEM_BYTES>>>(
        (const float*)d_in[0],  (const float*)d_in[1],  (const float*)d_in[2],
        (const float*)d_in[3],  (const float*)d_in[4],
        (const float*)d_in[5],  (const float*)d_in[7],  (const float*)d_in[8],
        (const float*)d_in[9],  (const float*)d_in[10],
        (const float*)d_in[11], (const float*)d_in[13], (const float*)d_in[14],
        (const float*)d_in[15], (const float*)d_in[16],
        (const float*)d_in[17], (const float*)d_in[18],
        (const float*)d_in[19], (const float*)d_in[20],
        (const float*)d_in[21], (const float*)d_in[22],
        (const float*)d_in[23], (const float*)d_in[24],
        (const float*)d_in[25], (const float*)d_in[26],
        (float*)d_out);
}

// round 9
// speedup vs baseline: 1.0647x; 1.0006x over previous
#include <cuda_runtime.h>
#include <cuda_bf16.h>
#include <math.h>

typedef unsigned long long ull;
#define DEVI __device__ __forceinline__

// ---------------- packed f32x2 FFMA2 (sm_103a) ----------------
DEVI void fma2(ull& d, ull a, ull b) {
    asm("fma.rn.f32x2 %0, %1, %2, %0;" : "+l"(d) : "l"(a), "l"(b));
}
DEVI float psum(ull a) {
    float x, y;
    asm("mov.b64 {%0,%1}, %2;" : "=f"(x), "=f"(y) : "l"(a));
    return x + y;
}

// ---------------- activations (precise) ----------------
DEVI float sigm(float x)  { return 1.f / (1.f + expf(-x)); }
DEVI float siluf(float x) { return x / (1.f + expf(-x)); }
DEVI float softpl(float x){ return fmaxf(x, 0.f) + log1pf(expf(-fabsf(x))); }
DEVI float geluf(float x) { return 0.5f * x * (1.f + erff(x * 0.70710678f)); }

// ---------------- problem constants ----------------
#define NBLK 128
#define TB   64
#define NTHR 256

// output element offsets
#define SCAL_OFF 0ull
#define K_OFF    73728ull
#define KI_OFF   81920ull
#define ST0_OFF  90112ull
#define ST1_OFF  67198976ull

// smem layout (floats) — 228,096 B => 1 CTA/SM
#define HS_OFF   0                          // hs  [64][132]
#define XS_OFF   (HS_OFF + 64*132)          // xss [64][260] (x tile stride 62 in input stage)
#define WS0_OFF  (XS_OFF + 64*260)          // ws0 [64][132] (w_in stride 62 in input stage)
#define WS1_OFF  (WS0_OFF + 64*132)         // ws1 [64][132]
#define TS_OFF   (WS1_OFF + 64*132)         // ts  [64][132] pre-LN scratch
#define BC_OFF   (TS_OFF + 64*132)          // bcs [64][66]
#define DTB_OFF  (BC_OFF + 64*66)           // dtB [64][36]
#define YA_OFF   (DTB_OFF + 64*36)          // ya  [64]
#define SMEM_FLOATS (YA_OFF + 64)
#define SMEM_BYTES  (SMEM_FLOATS * 4)

// ---------------- cp.async slab load: 64 rows x 128 cols -> stride 132 ----
DEVI void cpa_slab(float* ws, const float* __restrict__ g, int gld) {
    #pragma unroll
    for (int t = 0; t < 8; t++) {
        int idx = threadIdx.x + t * NTHR;     // 0..2047
        int r = idx >> 5, kq = idx & 31;
        unsigned sa = (unsigned)__cvta_generic_to_shared(ws + r*132 + kq*4);
        const float* gp = g + r*gld + kq*4;
        asm volatile("cp.async.cg.shared.global [%0], [%1], 16;" :: "r"(sa), "l"(gp));
    }
    asm volatile("cp.async.commit_group;" ::: "memory");
}
DEVI void cpa_wait() { asm volatile("cp.async.wait_group 0;" ::: "memory"); }

// ---- 64x64 chunk GEMM, K=128, thread tile 4x4 (warp tile 16x32).
// A: stride lda (broadcast loads). W: stride 132. vals +=.
DEVI void gemm64(const float* __restrict__ a, int lda, const float* __restrict__ w,
                 float vals[4][4], int row0, int col0) {
    ull acc[4][4];
    #pragma unroll
    for (int i = 0; i < 4; i++)
        #pragma unroll
        for (int j = 0; j < 4; j++) acc[i][j] = 0ull;
    #pragma unroll 4
    for (int k = 0; k < 128; k += 4) {
        ulonglong2 av[4], bv[4];
        #pragma unroll
        for (int i = 0; i < 4; i++) av[i] = *(const ulonglong2*)(a + (row0 + 4*i)*lda + k);
        #pragma unroll
        for (int j = 0; j < 4; j++) bv[j] = *(const ulonglong2*)(w + (col0 + 8*j)*132 + k);
        #pragma unroll
        for (int i = 0; i < 4; i++)
            #pragma unroll
            for (int j = 0; j < 4; j++) {
                fma2(acc[i][j], av[i].x, bv[j].x);
                fma2(acc[i][j], av[i].y, bv[j].y);
            }
    }
    #pragma unroll
    for (int i = 0; i < 4; i++)
        #pragma unroll
        for (int j = 0; j < 4; j++) vals[i][j] += psum(acc[i][j]);
}

// same, with D d-indices stored per k-step (streaming .cs state writes).
// xrow: thread's xss row base. p: thread's state base (row + quad offset).
// doff: starting global d (0..255). D=1 -> 32 d/chunk, D=2 -> 64 d/chunk.
template<int D>
DEVI void gemm64st(const float* __restrict__ a, int lda, const float* __restrict__ w,
                   float vals[4][4], int row0, int col0,
                   const float* __restrict__ xrow, float4 db0, float4 db1,
                   float* __restrict__ p, int doff) {
    ull acc[4][4];
    #pragma unroll
    for (int i = 0; i < 4; i++)
        #pragma unroll
        for (int j = 0; j < 4; j++) acc[i][j] = 0ull;
    #pragma unroll 4
    for (int k = 0; k < 128; k += 4) {
        ulonglong2 av[4], bv[4];
        #pragma unroll
        for (int i = 0; i < 4; i++) av[i] = *(const ulonglong2*)(a + (row0 + 4*i)*lda + k);
        #pragma unroll
        for (int j = 0; j < 4; j++) bv[j] = *(const ulonglong2*)(w + (col0 + 8*j)*132 + k);
        #pragma unroll
        for (int i = 0; i < 4; i++)
            #pragma unroll
            for (int j = 0; j < 4; j++) {
                fma2(acc[i][j], av[i].x, bv[j].x);
                fma2(acc[i][j], av[i].y, bv[j].y);
            }
        int t = k >> 2;
        #pragma unroll
        for (int q = 0; q < D; q++) {
            int d = doff + D*t + q;
            float xv = xrow[d];
            float4 v0; v0.x = xv*db0.x; v0.y = xv*db0.y; v0.z = xv*db0.z; v0.w = xv*db0.w;
            float4 v1; v1.x = xv*db1.x; v1.y = xv*db1.y; v1.z = xv*db1.z; v1.w = xv*db1.w;
            __stcs((float4*)(p + (unsigned)d*32u), v0);
            __stcs((float4*)(p + (unsigned)d*32u + 16u), v1);
        }
    }
    #pragma unroll
    for (int i = 0; i < 4; i++)
        #pragma unroll
        for (int j = 0; j < 4; j++) vals[i][j] += psum(acc[i][j]);
}

// per-row LayerNorm over 128 cols; warp w owns rows [8w, 8w+8).
DEVI void do_ln(float* hs, const float* src, int lds,
                const float* __restrict__ g, const float* __restrict__ b, bool addres) {
    int w = threadIdx.x >> 5, lane = threadIdx.x & 31;
    float4 gg = *(const float4*)(g + lane*4);
    float4 bb = *(const float4*)(b + lane*4);
    for (int r = w*8; r < w*8 + 8; r++) {
        float4 v = *(const float4*)(src + r*lds + lane*4);
        if (addres) {
            float4 h = *(const float4*)(hs + r*132 + lane*4);
            v.x += h.x; v.y += h.y; v.z += h.z; v.w += h.w;
        }
        float s = v.x + v.y + v.z + v.w;
        float q = v.x*v.x + v.y*v.y + v.z*v.z + v.w*v.w;
        #pragma unroll
        for (int o = 16; o > 0; o >>= 1) {
            s += __shfl_xor_sync(0xffffffffu, s, o);
            q += __shfl_xor_sync(0xffffffffu, q, o);
        }
        float m   = s * (1.f/128.f);
        float inv = rsqrtf(fmaxf(q * (1.f/128.f) - m*m, 0.f) + 1e-5f);
        float4 o4;
        o4.x = (v.x - m)*inv*gg.x + bb.x;
        o4.y = (v.y - m)*inv*gg.y + bb.y;
        o4.z = (v.z - m)*inv*gg.z + bb.z;
        o4.w = (v.w - m)*inv*gg.w + bb.w;
        *(float4*)(hs + r*132 + lane*4) = o4;
    }
}

// dt / B·C scalars, spread over all 256 threads (4 threads per row).
DEVI void dtdot(const float* hs, const float* bcs, float* dtBs, float* yav,
                const float* __restrict__ wdt) {
    int tid = threadIdx.x;
    int row = tid >> 2, part = tid & 3;
    float acc = 0.f;
    #pragma unroll 8
    for (int j = 0; j < 32; j++) {
        int k = part*32 + ((j + row + 8*part) & 31);   // conflict-free rotation
        acc += hs[row*132 + k] * __ldg(wdt + k);
    }
    acc += __shfl_xor_sync(0xffffffffu, acc, 1);
    acc += __shfl_xor_sync(0xffffffffu, acc, 2);
    float dt = softpl(acc);
    float bc = 0.f;
    #pragma unroll
    for (int i = 0; i < 8; i++) {
        int s = part*8 + i;
        float Bv = bcs[row*66 + s];
        bc += Bv * bcs[row*66 + 32 + s];
        dtBs[row*36 + s] = dt * Bv;
    }
    bc += __shfl_xor_sync(0xffffffffu, bc, 1);
    bc += __shfl_xor_sync(0xffffffffu, bc, 2);
    if (part == 0) yav[row] = dt * bc;
}

__global__ void __launch_bounds__(NTHR, 1) fused_kernel(
    const float* __restrict__ x,      const float* __restrict__ w_in,
    const float* __restrict__ b_in,   const float* __restrict__ ln_in_g,
    const float* __restrict__ ln_in_b,
    const float* __restrict__ in_w0,  const float* __restrict__ Dp0,
    const float* __restrict__ out_w0, const float* __restrict__ ln_g0,
    const float* __restrict__ ln_b0,
    const float* __restrict__ in_w1,  const float* __restrict__ Dp1,
    const float* __restrict__ out_w1, const float* __restrict__ ln_g1,
    const float* __restrict__ ln_b1,
    const float* __restrict__ fn_g,   const float* __restrict__ fn_b,
    const float* __restrict__ sh_w1,  const float* __restrict__ sh_b1,
    const float* __restrict__ sh_w2,  const float* __restrict__ sh_b2,
    const float* __restrict__ k_w,    const float* __restrict__ k_b,
    const float* __restrict__ ki_w,   const float* __restrict__ ki_b,
    float* __restrict__ outp)
{
    extern __shared__ float sm[];
    float* hs   = sm + HS_OFF;
    float* xss  = sm + XS_OFF;
    float* ws0  = sm + WS0_OFF;
    float* ws1  = sm + WS1_OFF;
    float* ts   = sm + TS_OFF;
    float* bcs  = sm + BC_OFF;
    float* dtBs = sm + DTB_OFF;
    float* yav  = sm + YA_OFF;

    const int tid  = threadIdx.x;
    const int wid  = tid >> 5, lane = tid & 31;
    const int wr   = wid & 3,  wcc  = wid >> 2;      // warp grid 4x2
    const int lr   = lane >> 3, lc  = lane & 7;      // lane grid 4x8
    const int row0 = wr*16 + lr;                     // rows row0 + 4i
    const int col0 = wcc*32 + lc;                    // cols col0 + 8j
    const int rowbase = blockIdx.x * TB;
    const int r_st = tid >> 2, q_st = tid & 3;       // state store: 1 row, quads q_st & q_st+4

    // ============ input stage: h = LN(x @ w_in^T + b_in) ============
    for (int idx = tid; idx < 64*58; idx += NTHR) {
        int r = idx / 58, k = idx - r*58;
        xss[r*62 + k] = x[(size_t)(rowbase + r)*58 + k];
    }
    for (int idx = tid; idx < 128*58; idx += NTHR) {
        int r = idx / 58, k = idx - r*58;
        ws0[r*62 + k] = w_in[idx];
    }
    __syncthreads();
    #pragma unroll 1
    for (int half = 0; half < 2; half++) {
        ull acc[4][4];
        #pragma unroll
        for (int i = 0; i < 4; i++)
            #pragma unroll
            for (int j = 0; j < 4; j++) acc[i][j] = 0ull;
        #pragma unroll 1
        for (int k = 0; k < 58; k += 2) {
            ull a[4], b[4];
            #pragma unroll
            for (int i = 0; i < 4; i++) a[i] = *(const ull*)(xss + (row0 + 4*i)*62 + k);
            #pragma unroll
            for (int j = 0; j < 4; j++) b[j] = *(const ull*)(ws0 + (half*64 + col0 + 8*j)*62 + k);
            #pragma unroll
            for (int i = 0; i < 4; i++)
                #pragma unroll
                for (int j = 0; j < 4; j++) fma2(acc[i][j], a[i], b[j]);
        }
        #pragma unroll
        for (int i = 0; i < 4; i++)
            #pragma unroll
            for (int j = 0; j < 4; j++) {
                int c = half*64 + col0 + 8*j;
                ts[(row0 + 4*i)*132 + c] = psum(acc[i][j]) + __ldg(b_in + c);
            }
    }
    __syncthreads();
    cpa_slab(ws1, in_w0 + 512*128, 128);           // L0 B|C slab; LN covers latency
    do_ln(hs, ts, 132, ln_in_g, ln_in_b, false);
    cpa_wait();
    __syncthreads();

    float* cur = ws1;
    float* nxt = ws0;

    // ============ two mamba layers ============
    const float* in_w_l[2]  = {in_w0, in_w1};
    const float* Dp_l[2]    = {Dp0, Dp1};
    const float* out_w_l[2] = {out_w0, out_w1};
    const float* g_l[2]     = {ln_g0, ln_g1};
    const float* b_l[2]     = {ln_b0, ln_b1};
    const ull    soff_l[2]  = {ST0_OFF, ST1_OFF};

    for (int L = 0; L < 2; L++) {
        const float* in_w  = in_w_l[L];
        const float* Dp    = Dp_l[L];
        const float* out_w = out_w_l[L];
        const ull    soff  = soff_l[L];
        // thread state base: row r_st, quads q_st (offset 4*q_st) and q_st+4 (+16)
        float* stb = outp + soff + (ull)(rowbase + r_st)*8192ull + (ull)(q_st*4);
        const float* xrb = xss + r_st*260;

        // ---- B|C chunk ----
        {
            cpa_slab(nxt, in_w + 256*128, 128);    // xs0
            float vals[4][4] = {};
            gemm64(hs, 132, cur, vals, row0, col0);
            #pragma unroll
            for (int i = 0; i < 4; i++)
                #pragma unroll
                for (int j = 0; j < 4; j++)
                    bcs[(row0 + 4*i)*66 + col0 + 8*j] = vals[i][j];
            cpa_wait(); __syncthreads();
            { float* t = cur; cur = nxt; nxt = t; }
        }

        // ---- xs chunks (proj cols 256..511) ----
        // carriers (global d cursor): xs1:D1@0, xs2:D2@32, xs3:D1@96,
        //                             z0:D2@128, z1:D1@192, z2:D1@224
        for (int sub = 0; sub < 4; sub++) {
            const float* nx = (sub < 3) ? (in_w + (320 + 64*sub)*128) : in_w;  // xs_{sub+1} else z0
            cpa_slab(nxt, nx, 128);
            if (sub == 0) dtdot(hs, bcs, dtBs, yav, in_w + 576*128);
            float vals[4][4] = {};
            if (sub == 0) gemm64(hs, 132, cur, vals, row0, col0);
            else {
                float4 db0 = *(const float4*)(dtBs + r_st*36 + q_st*4);
                float4 db1 = *(const float4*)(dtBs + r_st*36 + q_st*4 + 16);
                if (sub == 1)      gemm64st<1>(hs, 132, cur, vals, row0, col0, xrb, db0, db1, stb, 0);
                else if (sub == 2) gemm64st<2>(hs, 132, cur, vals, row0, col0, xrb, db0, db1, stb, 32);
                else               gemm64st<1>(hs, 132, cur, vals, row0, col0, xrb, db0, db1, stb, 96);
            }
            #pragma unroll
            for (int i = 0; i < 4; i++)
                #pragma unroll
                for (int j = 0; j < 4; j++)
                    xss[(row0 + 4*i)*260 + sub*64 + col0 + 8*j] = siluf(vals[i][j]);
            cpa_wait(); __syncthreads();
            { float* t = cur; cur = nxt; nxt = t; }
        }

        // ---- z chunks (proj cols 0..255) ----
        for (int sub = 0; sub < 4; sub++) {
            if (sub < 3) cpa_slab(nxt, in_w + 64*(sub+1)*128, 128);
            else         cpa_slab(nxt, out_w, 256);                 // o00
            float vals[4][4] = {};
            float4 db0 = *(const float4*)(dtBs + r_st*36 + q_st*4);
            float4 db1 = *(const float4*)(dtBs + r_st*36 + q_st*4 + 16);
            if (sub == 0)      gemm64st<2>(hs, 132, cur, vals, row0, col0, xrb, db0, db1, stb, 128);
            else if (sub == 1) gemm64st<1>(hs, 132, cur, vals, row0, col0, xrb, db0, db1, stb, 192);
            else if (sub == 2) gemm64st<1>(hs, 132, cur, vals, row0, col0, xrb, db0, db1, stb, 224);
            else               gemm64(hs, 132, cur, vals, row0, col0);
            #pragma unroll
            for (int i = 0; i < 4; i++)
                #pragma unroll
                for (int j = 0; j < 4; j++) {
                    int r = row0 + 4*i, c = sub*64 + col0 + 8*j;
                    float xv = xss[r*260 + c];
                    xss[r*260 + c] = siluf(vals[i][j]) * xv * (yav[r] + __ldg(Dp + c));
                }
            cpa_wait(); __syncthreads();
            { float* t = cur; cur = nxt; nxt = t; }
        }

        // ---- out GEMM: ts = u @ out_w^T (128 out cols; 4 slabs) ----
        for (int ch = 0; ch < 2; ch++) {
            float vals[4][4] = {};
            for (int kh = 0; kh < 2; kh++) {
                // prefetch next slab
                if (ch == 0 && kh == 0)      cpa_slab(nxt, out_w + 128, 256);
                else if (ch == 0 && kh == 1) cpa_slab(nxt, out_w + 64*256, 256);
                else if (ch == 1 && kh == 0) cpa_slab(nxt, out_w + 64*256 + 128, 256);
                else cpa_slab(nxt, (L == 0) ? (in_w1 + 512*128) : sh_w1, 128);
                gemm64(xss + kh*128, 260, cur, vals, row0, col0);
                if (kh == 1) {
                    #pragma unroll
                    for (int i = 0; i < 4; i++)
                        #pragma unroll
                        for (int j = 0; j < 4; j++)
                            ts[(row0 + 4*i)*132 + ch*64 + col0 + 8*j] = vals[i][j];
                }
                cpa_wait(); __syncthreads();
                { float* t = cur; cur = nxt; nxt = t; }
            }
        }
        do_ln(hs, ts, 132, g_l[L], b_l[L], true);   // h = LN(h + out)
        __syncthreads();
    }

    // ============ final LN + heads ============
    do_ln(hs, hs, 132, fn_g, fn_b, false);
    __syncthreads();

    // t1 = gelu(h @ sh_w1^T + sh_b1) -> bcs; sh_w1 is in cur
    {
        float vals[4][4] = {};
        gemm64(hs, 132, cur, vals, row0, col0);
        #pragma unroll
        for (int i = 0; i < 4; i++)
            #pragma unroll
            for (int j = 0; j < 4; j++) {
                int c = col0 + 8*j;
                bcs[(row0 + 4*i)*66 + c] = geluf(vals[i][j] + __ldg(sh_b1 + c));
            }
    }
    __syncthreads();

    // scaling = softplus(t1 @ sh_w2^T + sh_b2)  (9 cols)
    for (int idx = tid; idx < 64*9; idx += NTHR) {
        int r = idx / 9, c = idx - r*9;
        float acc = __ldg(sh_b2 + c);
        #pragma unroll 4
        for (int ss = 0; ss < 64; ss++) {
            int s = (ss + tid) & 63;
            acc += bcs[r*66 + s] * __ldg(sh_w2 + c*64 + s);
        }
        outp[SCAL_OFF + (ull)(rowbase + r)*9ull + c] = softpl(acc);
    }

    // K, K_internal (per-row dots over h)
    if (tid < 64) {
        float a0 = 0.f, a1 = 0.f;
        #pragma unroll 4
        for (int kk = 0; kk < 128; kk++) {
            int k = (kk + tid) & 127;
            float hv = hs[tid*132 + k];
            a0 += hv * __ldg(k_w + k);
            a1 += hv * __ldg(ki_w + k);
        }
        outp[K_OFF  + (ull)(rowbase + tid)] = sigm(a0 + __ldg(k_b));
        outp[KI_OFF + (ull)(rowbase + tid)] = sigm(a1 + __ldg(ki_b));
    }
}

extern "C" void kernel_launch(void* const* d_in, const int* in_sizes, int n_in,
                              void* d_out, int out_size) {
    (void)in_sizes; (void)n_in; (void)out_size;
    cudaFuncSetAttribute(fused_kernel, cudaFuncAttributeMaxDynamicSharedMemorySize, SMEM_BYTES);
    fused_kernel<<<NBLK, NTHR, SMEM_BYTES>>>(
        (const float*)d_in[0],  (const float*)d_in[1],  (const float*)d_in[2],
        (const float*)d_in[3],  (const float*)d_in[4],
        (const float*)d_in[5],  (const float*)d_in[7],  (const float*)d_in[8],
        (const float*)d_in[9],  (const float*)d_in[10],
        (const float*)d_in[11], (const float*)d_in[13], (const float*)d_in[14],
        (const float*)d_in[15], (const float*)d_in[16],
        (const float*)d_in[17], (const float*)d_in[18],
        (const float*)d_in[19], (const float*)d_in[20],
        (const float*)d_in[21], (const float*)d_in[22],
        (const float*)d_in[23], (const float*)d_in[24],
        (const float*)d_in[25], (const float*)d_in[26],
        (float*)d_out);
}

// round 10
// speedup vs baseline: 1.0731x; 1.0079x over previous
#include <cuda_runtime.h>
#include <cuda_bf16.h>
#include <math.h>

typedef unsigned long long ull;
#define DEVI __device__ __forceinline__

// ---------------- packed f32x2 FFMA2 (sm_103a) ----------------
DEVI void fma2(ull& d, ull a, ull b) {
    asm("fma.rn.f32x2 %0, %1, %2, %0;" : "+l"(d) : "l"(a), "l"(b));
}
DEVI float psum(ull a) {
    float x, y;
    asm("mov.b64 {%0,%1}, %2;" : "=f"(x), "=f"(y) : "l"(a));
    return x + y;
}

// ---------------- activations (precise) ----------------
DEVI float sigm(float x)  { return 1.f / (1.f + expf(-x)); }
DEVI float siluf(float x) { return x / (1.f + expf(-x)); }
DEVI float softpl(float x){ return fmaxf(x, 0.f) + log1pf(expf(-fabsf(x))); }
DEVI float geluf(float x) { return 0.5f * x * (1.f + erff(x * 0.70710678f)); }

// ---------------- problem constants ----------------
#define NBLK 128
#define TB   64
#define NTHR 256

// output element offsets
#define SCAL_OFF 0ull
#define K_OFF    73728ull
#define KI_OFF   81920ull
#define ST0_OFF  90112ull
#define ST1_OFF  67198976ull

// smem layout (floats) — 228,096 B => 1 CTA/SM
#define HS_OFF   0                          // hs  [64][132]
#define XS_OFF   (HS_OFF + 64*132)          // xss [64][260] (x tile stride 62 in input stage)
#define WS0_OFF  (XS_OFF + 64*260)          // ws0 [64][132] (w_in stride 62 in input stage)
#define WS1_OFF  (WS0_OFF + 64*132)         // ws1 [64][132]
#define TS_OFF   (WS1_OFF + 64*132)         // ts  [64][132] pre-LN scratch
#define BC_OFF   (TS_OFF + 64*132)          // bcs [64][66]
#define DTB_OFF  (BC_OFF + 64*66)           // dtB [64][36]
#define YA_OFF   (DTB_OFF + 64*36)          // ya  [64]
#define SMEM_FLOATS (YA_OFF + 64)
#define SMEM_BYTES  (SMEM_FLOATS * 4)

// ---------------- cp.async slab load: 64 rows x 128 cols -> stride 132 ----
DEVI void cpa_slab(float* ws, const float* __restrict__ g, int gld) {
    #pragma unroll
    for (int t = 0; t < 8; t++) {
        int idx = threadIdx.x + t * NTHR;     // 0..2047
        int r = idx >> 5, kq = idx & 31;
        unsigned sa = (unsigned)__cvta_generic_to_shared(ws + r*132 + kq*4);
        const float* gp = g + r*gld + kq*4;
        asm volatile("cp.async.cg.shared.global [%0], [%1], 16;" :: "r"(sa), "l"(gp));
    }
    asm volatile("cp.async.commit_group;" ::: "memory");
}
DEVI void cpa_wait() { asm volatile("cp.async.wait_group 0;" ::: "memory"); }

// ---- 64x64 chunk GEMM, K=128, thread tile 4x4 (warp tile 16x32).
// A: stride lda (broadcast loads). W: stride 132. vals +=.
DEVI void gemm64(const float* __restrict__ a, int lda, const float* __restrict__ w,
                 float vals[4][4], int row0, int col0) {
    ull acc[4][4];
    #pragma unroll
    for (int i = 0; i < 4; i++)
        #pragma unroll
        for (int j = 0; j < 4; j++) acc[i][j] = 0ull;
    #pragma unroll 4
    for (int k = 0; k < 128; k += 4) {
        ulonglong2 av[4], bv[4];
        #pragma unroll
        for (int i = 0; i < 4; i++) av[i] = *(const ulonglong2*)(a + (row0 + 4*i)*lda + k);
        #pragma unroll
        for (int j = 0; j < 4; j++) bv[j] = *(const ulonglong2*)(w + (col0 + 8*j)*132 + k);
        #pragma unroll
        for (int i = 0; i < 4; i++)
            #pragma unroll
            for (int j = 0; j < 4; j++) {
                fma2(acc[i][j], av[i].x, bv[j].x);
                fma2(acc[i][j], av[i].y, bv[j].y);
            }
    }
    #pragma unroll
    for (int i = 0; i < 4; i++)
        #pragma unroll
        for (int j = 0; j < 4; j++) vals[i][j] += psum(acc[i][j]);
}

// same, with D d-indices stored per k-step (streaming .cs state writes).
// xrow: thread's xss row base. p: thread's state base (row + quad offset).
// doff: starting global d (0..255). D=1 -> 32 d/chunk, D=2 -> 64 d/chunk.
template<int D>
DEVI void gemm64st(const float* __restrict__ a, int lda, const float* __restrict__ w,
                   float vals[4][4], int row0, int col0,
                   const float* __restrict__ xrow, float4 db0, float4 db1,
                   float* __restrict__ p, int doff) {
    ull acc[4][4];
    #pragma unroll
    for (int i = 0; i < 4; i++)
        #pragma unroll
        for (int j = 0; j < 4; j++) acc[i][j] = 0ull;
    #pragma unroll 4
    for (int k = 0; k < 128; k += 4) {
        ulonglong2 av[4], bv[4];
        #pragma unroll
        for (int i = 0; i < 4; i++) av[i] = *(const ulonglong2*)(a + (row0 + 4*i)*lda + k);
        #pragma unroll
        for (int j = 0; j < 4; j++) bv[j] = *(const ulonglong2*)(w + (col0 + 8*j)*132 + k);
        #pragma unroll
        for (int i = 0; i < 4; i++)
            #pragma unroll
            for (int j = 0; j < 4; j++) {
                fma2(acc[i][j], av[i].x, bv[j].x);
                fma2(acc[i][j], av[i].y, bv[j].y);
            }
        int t = k >> 2;
        #pragma unroll
        for (int q = 0; q < D; q++) {
            int d = doff + D*t + q;
            float xv = xrow[d];
            float4 v0; v0.x = xv*db0.x; v0.y = xv*db0.y; v0.z = xv*db0.z; v0.w = xv*db0.w;
            float4 v1; v1.x = xv*db1.x; v1.y = xv*db1.y; v1.z = xv*db1.z; v1.w = xv*db1.w;
            __stcs((float4*)(p + (unsigned)d*32u), v0);
            __stcs((float4*)(p + (unsigned)d*32u + 16u), v1);
        }
    }
    #pragma unroll
    for (int i = 0; i < 4; i++)
        #pragma unroll
        for (int j = 0; j < 4; j++) vals[i][j] += psum(acc[i][j]);
}

// per-row LayerNorm over 128 cols; warp w owns rows [8w, 8w+8).
DEVI void do_ln(float* hs, const float* src, int lds,
                const float* __restrict__ g, const float* __restrict__ b, bool addres) {
    int w = threadIdx.x >> 5, lane = threadIdx.x & 31;
    float4 gg = *(const float4*)(g + lane*4);
    float4 bb = *(const float4*)(b + lane*4);
    for (int r = w*8; r < w*8 + 8; r++) {
        float4 v = *(const float4*)(src + r*lds + lane*4);
        if (addres) {
            float4 h = *(const float4*)(hs + r*132 + lane*4);
            v.x += h.x; v.y += h.y; v.z += h.z; v.w += h.w;
        }
        float s = v.x + v.y + v.z + v.w;
        float q = v.x*v.x + v.y*v.y + v.z*v.z + v.w*v.w;
        #pragma unroll
        for (int o = 16; o > 0; o >>= 1) {
            s += __shfl_xor_sync(0xffffffffu, s, o);
            q += __shfl_xor_sync(0xffffffffu, q, o);
        }
        float m   = s * (1.f/128.f);
        float inv = rsqrtf(fmaxf(q * (1.f/128.f) - m*m, 0.f) + 1e-5f);
        float4 o4;
        o4.x = (v.x - m)*inv*gg.x + bb.x;
        o4.y = (v.y - m)*inv*gg.y + bb.y;
        o4.z = (v.z - m)*inv*gg.z + bb.z;
        o4.w = (v.w - m)*inv*gg.w + bb.w;
        *(float4*)(hs + r*132 + lane*4) = o4;
    }
}

// dt / B·C scalars, spread over all 256 threads (4 threads per row).
DEVI void dtdot(const float* hs, const float* bcs, float* dtBs, float* yav,
                const float* __restrict__ wdt) {
    int tid = threadIdx.x;
    int row = tid >> 2, part = tid & 3;
    float acc = 0.f;
    #pragma unroll 8
    for (int j = 0; j < 32; j++) {
        int k = part*32 + ((j + row + 8*part) & 31);   // conflict-free rotation
        acc += hs[row*132 + k] * __ldg(wdt + k);
    }
    acc += __shfl_xor_sync(0xffffffffu, acc, 1);
    acc += __shfl_xor_sync(0xffffffffu, acc, 2);
    float dt = softpl(acc);
    float bc = 0.f;
    #pragma unroll
    for (int i = 0; i < 8; i++) {
        int s = part*8 + i;
        float Bv = bcs[row*66 + s];
        bc += Bv * bcs[row*66 + 32 + s];
        dtBs[row*36 + s] = dt * Bv;
    }
    bc += __shfl_xor_sync(0xffffffffu, bc, 1);
    bc += __shfl_xor_sync(0xffffffffu, bc, 2);
    if (part == 0) yav[row] = dt * bc;
}

__global__ void __launch_bounds__(NTHR, 1) fused_kernel(
    const float* __restrict__ x,      const float* __restrict__ w_in,
    const float* __restrict__ b_in,   const float* __restrict__ ln_in_g,
    const float* __restrict__ ln_in_b,
    const float* __restrict__ in_w0,  const float* __restrict__ Dp0,
    const float* __restrict__ out_w0, const float* __restrict__ ln_g0,
    const float* __restrict__ ln_b0,
    const float* __restrict__ in_w1,  const float* __restrict__ Dp1,
    const float* __restrict__ out_w1, const float* __restrict__ ln_g1,
    const float* __restrict__ ln_b1,
    const float* __restrict__ fn_g,   const float* __restrict__ fn_b,
    const float* __restrict__ sh_w1,  const float* __restrict__ sh_b1,
    const float* __restrict__ sh_w2,  const float* __restrict__ sh_b2,
    const float* __restrict__ k_w,    const float* __restrict__ k_b,
    const float* __restrict__ ki_w,   const float* __restrict__ ki_b,
    float* __restrict__ outp)
{
    extern __shared__ float sm[];
    float* hs   = sm + HS_OFF;
    float* xss  = sm + XS_OFF;
    float* ws0  = sm + WS0_OFF;
    float* ws1  = sm + WS1_OFF;
    float* ts   = sm + TS_OFF;
    float* bcs  = sm + BC_OFF;
    float* dtBs = sm + DTB_OFF;
    float* yav  = sm + YA_OFF;

    const int tid  = threadIdx.x;
    const int wid  = tid >> 5, lane = tid & 31;
    const int wr   = wid & 3,  wcc  = wid >> 2;      // warp grid 4x2
    const int lr   = lane >> 3, lc  = lane & 7;      // lane grid 4x8
    const int row0 = wr*16 + lr;                     // rows row0 + 4i
    const int col0 = wcc*32 + lc;                    // cols col0 + 8j
    const int rowbase = blockIdx.x * TB;
    const int r_st = tid >> 2, q_st = tid & 3;       // state store: 1 row, quads q_st & q_st+4

    // ============ input stage: h = LN(x @ w_in^T + b_in) ============
    for (int idx = tid; idx < 64*58; idx += NTHR) {
        int r = idx / 58, k = idx - r*58;
        xss[r*62 + k] = x[(size_t)(rowbase + r)*58 + k];
    }
    for (int idx = tid; idx < 128*58; idx += NTHR) {
        int r = idx / 58, k = idx - r*58;
        ws0[r*62 + k] = w_in[idx];
    }
    __syncthreads();
    #pragma unroll 1
    for (int half = 0; half < 2; half++) {
        ull acc[4][4];
        #pragma unroll
        for (int i = 0; i < 4; i++)
            #pragma unroll
            for (int j = 0; j < 4; j++) acc[i][j] = 0ull;
        #pragma unroll 1
        for (int k = 0; k < 58; k += 2) {
            ull a[4], b[4];
            #pragma unroll
            for (int i = 0; i < 4; i++) a[i] = *(const ull*)(xss + (row0 + 4*i)*62 + k);
            #pragma unroll
            for (int j = 0; j < 4; j++) b[j] = *(const ull*)(ws0 + (half*64 + col0 + 8*j)*62 + k);
            #pragma unroll
            for (int i = 0; i < 4; i++)
                #pragma unroll
                for (int j = 0; j < 4; j++) fma2(acc[i][j], a[i], b[j]);
        }
        #pragma unroll
        for (int i = 0; i < 4; i++)
            #pragma unroll
            for (int j = 0; j < 4; j++) {
                int c = half*64 + col0 + 8*j;
                ts[(row0 + 4*i)*132 + c] = psum(acc[i][j]) + __ldg(b_in + c);
            }
    }
    __syncthreads();
    cpa_slab(ws1, in_w0 + 512*128, 128);           // L0 B|C slab; LN covers latency
    do_ln(hs, ts, 132, ln_in_g, ln_in_b, false);
    cpa_wait();
    __syncthreads();

    float* cur = ws1;
    float* nxt = ws0;

    // ============ two mamba layers ============
    const float* in_w_l[2]  = {in_w0, in_w1};
    const float* Dp_l[2]    = {Dp0, Dp1};
    const float* out_w_l[2] = {out_w0, out_w1};
    const float* g_l[2]     = {ln_g0, ln_g1};
    const float* b_l[2]     = {ln_b0, ln_b1};
    const ull    soff_l[2]  = {ST0_OFF, ST1_OFF};

    for (int L = 0; L < 2; L++) {
        const float* in_w  = in_w_l[L];
        const float* Dp    = Dp_l[L];
        const float* out_w = out_w_l[L];
        const ull    soff  = soff_l[L];
        // thread state base: row r_st, quads q_st (offset 4*q_st) and q_st+4 (+16)
        float* stb = outp + soff + (ull)(rowbase + r_st)*8192ull + (ull)(q_st*4);
        const float* xrb = xss + r_st*260;

        // ---- B|C chunk ----
        {
            cpa_slab(nxt, in_w + 256*128, 128);    // xs0
            float vals[4][4] = {};
            gemm64(hs, 132, cur, vals, row0, col0);
            #pragma unroll
            for (int i = 0; i < 4; i++)
                #pragma unroll
                for (int j = 0; j < 4; j++)
                    bcs[(row0 + 4*i)*66 + col0 + 8*j] = vals[i][j];
            cpa_wait(); __syncthreads();
            { float* t = cur; cur = nxt; nxt = t; }
        }

        // ---- xs chunks (proj cols 256..511) ----
        // carriers (global d cursor): xs1:D1@0, xs2:D2@32, xs3:D1@96,
        //                             z0:D2@128, z1:D1@192, z2:D1@224
        for (int sub = 0; sub < 4; sub++) {
            const float* nx = (sub < 3) ? (in_w + (320 + 64*sub)*128) : in_w;  // xs_{sub+1} else z0
            cpa_slab(nxt, nx, 128);
            if (sub == 0) dtdot(hs, bcs, dtBs, yav, in_w + 576*128);
            float vals[4][4] = {};
            if (sub == 0) gemm64(hs, 132, cur, vals, row0, col0);
            else {
                float4 db0 = *(const float4*)(dtBs + r_st*36 + q_st*4);
                float4 db1 = *(const float4*)(dtBs + r_st*36 + q_st*4 + 16);
                if (sub == 1)      gemm64st<1>(hs, 132, cur, vals, row0, col0, xrb, db0, db1, stb, 0);
                else if (sub == 2) gemm64st<2>(hs, 132, cur, vals, row0, col0, xrb, db0, db1, stb, 32);
                else               gemm64st<1>(hs, 132, cur, vals, row0, col0, xrb, db0, db1, stb, 96);
            }
            #pragma unroll
            for (int i = 0; i < 4; i++)
                #pragma unroll
                for (int j = 0; j < 4; j++)
                    xss[(row0 + 4*i)*260 + sub*64 + col0 + 8*j] = siluf(vals[i][j]);
            cpa_wait(); __syncthreads();
            { float* t = cur; cur = nxt; nxt = t; }
        }

        // ---- z chunks (proj cols 0..255) ----
        for (int sub = 0; sub < 4; sub++) {
            if (sub < 3) cpa_slab(nxt, in_w + 64*(sub+1)*128, 128);
            else         cpa_slab(nxt, out_w, 256);                 // o00
            float vals[4][4] = {};
            float4 db0 = *(const float4*)(dtBs + r_st*36 + q_st*4);
            float4 db1 = *(const float4*)(dtBs + r_st*36 + q_st*4 + 16);
            if (sub == 0)      gemm64st<2>(hs, 132, cur, vals, row0, col0, xrb, db0, db1, stb, 128);
            else if (sub == 1) gemm64st<1>(hs, 132, cur, vals, row0, col0, xrb, db0, db1, stb, 192);
            else if (sub == 2) gemm64st<1>(hs, 132, cur, vals, row0, col0, xrb, db0, db1, stb, 224);
            else               gemm64(hs, 132, cur, vals, row0, col0);
            #pragma unroll
            for (int i = 0; i < 4; i++)
                #pragma unroll
                for (int j = 0; j < 4; j++) {
                    int r = row0 + 4*i, c = sub*64 + col0 + 8*j;
                    float xv = xss[r*260 + c];
                    xss[r*260 + c] = siluf(vals[i][j]) * xv * (yav[r] + __ldg(Dp + c));
                }
            cpa_wait(); __syncthreads();
            { float* t = cur; cur = nxt; nxt = t; }
        }

        // ---- out GEMM: ts = u @ out_w^T (128 out cols; 4 slabs) ----
        for (int ch = 0; ch < 2; ch++) {
            float vals[4][4] = {};
            for (int kh = 0; kh < 2; kh++) {
                // prefetch next slab
                if (ch == 0 && kh == 0)      cpa_slab(nxt, out_w + 128, 256);
                else if (ch == 0 && kh == 1) cpa_slab(nxt, out_w + 64*256, 256);
                else if (ch == 1 && kh == 0) cpa_slab(nxt, out_w + 64*256 + 128, 256);
                else cpa_slab(nxt, (L == 0) ? (in_w1 + 512*128) : sh_w1, 128);
                gemm64(xss + kh*128, 260, cur, vals, row0, col0);
                if (kh == 1) {
                    #pragma unroll
                    for (int i = 0; i < 4; i++)
                        #pragma unroll
                        for (int j = 0; j < 4; j++)
                            ts[(row0 + 4*i)*132 + ch*64 + col0 + 8*j] = vals[i][j];
                }
                cpa_wait(); __syncthreads();
                { float* t = cur; cur = nxt; nxt = t; }
            }
        }
        do_ln(hs, ts, 132, g_l[L], b_l[L], true);   // h = LN(h + out)
        __syncthreads();
    }

    // ============ final LN + heads ============
    do_ln(hs, hs, 132, fn_g, fn_b, false);
    __syncthreads();

    // t1 = gelu(h @ sh_w1^T + sh_b1) -> bcs; sh_w1 is in cur
    {
        float vals[4][4] = {};
        gemm64(hs, 132, cur, vals, row0, col0);
        #pragma unroll
        for (int i = 0; i < 4; i++)
            #pragma unroll
            for (int j = 0; j < 4; j++) {
                int c = col0 + 8*j;
                bcs[(row0 + 4*i)*66 + c] = geluf(vals[i][j] + __ldg(sh_b1 + c));
            }
    }
    __syncthreads();

    // scaling = softplus(t1 @ sh_w2^T + sh_b2)  (9 cols)
    for (int idx = tid; idx < 64*9; idx += NTHR) {
        int r = idx / 9, c = idx - r*9;
        float acc = __ldg(sh_b2 + c);
        #pragma unroll 4
        for (int ss = 0; ss < 64; ss++) {
            int s = (ss + tid) & 63;
            acc += bcs[r*66 + s] * __ldg(sh_w2 + c*64 + s);
        }
        outp[SCAL_OFF + (ull)(rowbase + r)*9ull + c] = softpl(acc);
    }

    // K, K_internal (per-row dots over h)
    if (tid < 64) {
        float a0 = 0.f, a1 = 0.f;
        #pragma unroll 4
        for (int kk = 0; kk < 128; kk++) {
            int k = (kk + tid) & 127;
            float hv = hs[tid*132 + k];
            a0 += hv * __ldg(k_w + k);
            a1 += hv * __ldg(ki_w + k);
        }
        outp[K_OFF  + (ull)(rowbase + tid)] = sigm(a0 + __ldg(k_b));
        outp[KI_OFF + (ull)(rowbase + tid)] = sigm(a1 + __ldg(ki_b));
    }
}

extern "C" void kernel_launch(void* const* d_in, const int* in_sizes, int n_in,
                              void* d_out, int out_size) {
    (void)in_sizes; (void)n_in; (void)out_size;
    cudaFuncSetAttribute(fused_kernel, cudaFuncAttributeMaxDynamicSharedMemorySize, SMEM_BYTES);
    fused_kernel<<<NBLK, NTHR, SMEM_BYTES>>>(
        (const float*)d_in[0],  (const float*)d_in[1],  (const float*)d_in[2],
        (const float*)d_in[3],  (const float*)d_in[4],
        (const float*)d_in[5],  (const float*)d_in[7],  (const float*)d_in[8],
        (const float*)d_in[9],  (const float*)d_in[10],
        (const float*)d_in[11], (const float*)d_in[13], (const float*)d_in[14],
        (const float*)d_in[15], (const float*)d_in[16],
        (const float*)d_in[17], (const float*)d_in[18],
        (const float*)d_in[19], (const float*)d_in[20],
        (const float*)d_in[21], (const float*)d_in[22],
        (const float*)d_in[23], (const float*)d_in[24],
        (const float*)d_in[25], (const float*)d_in[26],
        (float*)d_out);
}

// round 11
// speedup vs baseline: 1.1322x; 1.0551x over previous
#include <cuda_runtime.h>
#include <cuda_bf16.h>
#include <math.h>

typedef unsigned long long ull;
#define DEVI __device__ __forceinline__

// ---------------- packed f32x2 FFMA2 (sm_103a) ----------------
DEVI void fma2(ull& d, ull a, ull b) {
    asm("fma.rn.f32x2 %0, %1, %2, %0;" : "+l"(d) : "l"(a), "l"(b));
}
DEVI float psum(ull a) {
    float x, y;
    asm("mov.b64 {%0,%1}, %2;" : "=f"(x), "=f"(y) : "l"(a));
    return x + y;
}

// ---------------- activations (precise) ----------------
DEVI float sigm(float x)  { return 1.f / (1.f + expf(-x)); }
DEVI float siluf(float x) { return x / (1.f + expf(-x)); }
DEVI float softpl(float x){ return fmaxf(x, 0.f) + log1pf(expf(-fabsf(x))); }
DEVI float geluf(float x) { return 0.5f * x * (1.f + erff(x * 0.70710678f)); }

// ---------------- problem constants ----------------
#define NBLK 128
#define TB   64
#define NTHR 256

// output element offsets
#define SCAL_OFF 0ull
#define K_OFF    73728ull
#define KI_OFF   81920ull
#define ST0_OFF  90112ull
#define ST1_OFF  67198976ull

// smem layout (floats) — 228,096 B => 1 CTA/SM
#define HS_OFF   0                          // hs  [64][132]
#define XS_OFF   (HS_OFF + 64*132)          // xss [64][260]
#define WS0_OFF  (XS_OFF + 64*260)          // ws0 [64][132]
#define WS1_OFF  (WS0_OFF + 64*132)         // ws1 [64][132]
#define TS_OFF   (WS1_OFF + 64*132)         // ts  [64][132]
#define BC_OFF   (TS_OFF + 64*132)          // bcs [64][66]
#define DTB_OFF  (BC_OFF + 64*66)           // dtB [64][36]
#define YA_OFF   (DTB_OFF + 64*36)          // ya  [64]
#define SMEM_FLOATS (YA_OFF + 64)
#define SMEM_BYTES  (SMEM_FLOATS * 4)

// ---------------- cp.async slab load: 64 rows x 128 cols -> stride 132 ----
DEVI void cpa_slab(float* ws, const float* __restrict__ g, int gld) {
    #pragma unroll
    for (int t = 0; t < 8; t++) {
        int idx = threadIdx.x + t * NTHR;     // 0..2047
        int r = idx >> 5, kq = idx & 31;
        unsigned sa = (unsigned)__cvta_generic_to_shared(ws + r*132 + kq*4);
        const float* gp = g + r*gld + kq*4;
        asm volatile("cp.async.cg.shared.global [%0], [%1], 16;" :: "r"(sa), "l"(gp));
    }
    asm volatile("cp.async.commit_group;" ::: "memory");
}
DEVI void cpa_wait() { asm volatile("cp.async.wait_group 0;" ::: "memory"); }

// ---- 64x64 chunk GEMM, K=128, thread tile 4x4 (warp tile 16x32).
DEVI void gemm64(const float* __restrict__ a, int lda, const float* __restrict__ w,
                 float vals[4][4], int row0, int col0) {
    ull acc[4][4];
    #pragma unroll
    for (int i = 0; i < 4; i++)
        #pragma unroll
        for (int j = 0; j < 4; j++) acc[i][j] = 0ull;
    #pragma unroll 4
    for (int k = 0; k < 128; k += 4) {
        ulonglong2 av[4], bv[4];
        #pragma unroll
        for (int i = 0; i < 4; i++) av[i] = *(const ulonglong2*)(a + (row0 + 4*i)*lda + k);
        #pragma unroll
        for (int j = 0; j < 4; j++) bv[j] = *(const ulonglong2*)(w + (col0 + 8*j)*132 + k);
        #pragma unroll
        for (int i = 0; i < 4; i++)
            #pragma unroll
            for (int j = 0; j < 4; j++) {
                fma2(acc[i][j], av[i].x, bv[j].x);
                fma2(acc[i][j], av[i].y, bv[j].y);
            }
    }
    #pragma unroll
    for (int i = 0; i < 4; i++)
        #pragma unroll
        for (int j = 0; j < 4; j++) vals[i][j] += psum(acc[i][j]);
}

// same, with D d-indices stored per k-step. Thread owns rows rA=tid>>3 and
// rB=rA+32, quad sq=tid&7 — per warp STG.128: 4 FULLY covered 128B lines.
template<int D>
DEVI void gemm64st(const float* __restrict__ a, int lda, const float* __restrict__ w,
                   float vals[4][4], int row0, int col0,
                   const float* __restrict__ xrA, const float* __restrict__ xrB,
                   float4 dbA, float4 dbB,
                   float* __restrict__ pA, float* __restrict__ pB, int doff) {
    ull acc[4][4];
    #pragma unroll
    for (int i = 0; i < 4; i++)
        #pragma unroll
        for (int j = 0; j < 4; j++) acc[i][j] = 0ull;
    #pragma unroll 4
    for (int k = 0; k < 128; k += 4) {
        ulonglong2 av[4], bv[4];
        #pragma unroll
        for (int i = 0; i < 4; i++) av[i] = *(const ulonglong2*)(a + (row0 + 4*i)*lda + k);
        #pragma unroll
        for (int j = 0; j < 4; j++) bv[j] = *(const ulonglong2*)(w + (col0 + 8*j)*132 + k);
        #pragma unroll
        for (int i = 0; i < 4; i++)
            #pragma unroll
            for (int j = 0; j < 4; j++) {
                fma2(acc[i][j], av[i].x, bv[j].x);
                fma2(acc[i][j], av[i].y, bv[j].y);
            }
        int t = k >> 2;
        #pragma unroll
        for (int q = 0; q < D; q++) {
            int d = doff + D*t + q;
            float xvA = xrA[d];
            float4 vA; vA.x = xvA*dbA.x; vA.y = xvA*dbA.y; vA.z = xvA*dbA.z; vA.w = xvA*dbA.w;
            __stcs((float4*)(pA + (unsigned)d*32u), vA);
            float xvB = xrB[d];
            float4 vB; vB.x = xvB*dbB.x; vB.y = xvB*dbB.y; vB.z = xvB*dbB.z; vB.w = xvB*dbB.w;
            __stcs((float4*)(pB + (unsigned)d*32u), vB);
        }
    }
    #pragma unroll
    for (int i = 0; i < 4; i++)
        #pragma unroll
        for (int j = 0; j < 4; j++) vals[i][j] += psum(acc[i][j]);
}

// per-row LayerNorm over 128 cols; warp w owns rows [8w, 8w+8).
DEVI void do_ln(float* hs, const float* src, int lds,
                const float* __restrict__ g, const float* __restrict__ b, bool addres) {
    int w = threadIdx.x >> 5, lane = threadIdx.x & 31;
    float4 gg = *(const float4*)(g + lane*4);
    float4 bb = *(const float4*)(b + lane*4);
    for (int r = w*8; r < w*8 + 8; r++) {
        float4 v = *(const float4*)(src + r*lds + lane*4);
        if (addres) {
            float4 h = *(const float4*)(hs + r*132 + lane*4);
            v.x += h.x; v.y += h.y; v.z += h.z; v.w += h.w;
        }
        float s = v.x + v.y + v.z + v.w;
        float q = v.x*v.x + v.y*v.y + v.z*v.z + v.w*v.w;
        #pragma unroll
        for (int o = 16; o > 0; o >>= 1) {
            s += __shfl_xor_sync(0xffffffffu, s, o);
            q += __shfl_xor_sync(0xffffffffu, q, o);
        }
        float m   = s * (1.f/128.f);
        float inv = rsqrtf(fmaxf(q * (1.f/128.f) - m*m, 0.f) + 1e-5f);
        float4 o4;
        o4.x = (v.x - m)*inv*gg.x + bb.x;
        o4.y = (v.y - m)*inv*gg.y + bb.y;
        o4.z = (v.z - m)*inv*gg.z + bb.z;
        o4.w = (v.w - m)*inv*gg.w + bb.w;
        *(float4*)(hs + r*132 + lane*4) = o4;
    }
}

// dt / B·C scalars, spread over all 256 threads (4 threads per row).
DEVI void dtdot(const float* hs, const float* bcs, float* dtBs, float* yav,
                const float* __restrict__ wdt) {
    int tid = threadIdx.x;
    int row = tid >> 2, part = tid & 3;
    float acc = 0.f;
    #pragma unroll 8
    for (int j = 0; j < 32; j++) {
        int k = part*32 + ((j + row + 8*part) & 31);   // conflict-free rotation
        acc += hs[row*132 + k] * __ldg(wdt + k);
    }
    acc += __shfl_xor_sync(0xffffffffu, acc, 1);
    acc += __shfl_xor_sync(0xffffffffu, acc, 2);
    float dt = softpl(acc);
    float bc = 0.f;
    #pragma unroll
    for (int i = 0; i < 8; i++) {
        int s = part*8 + i;
        float Bv = bcs[row*66 + s];
        bc += Bv * bcs[row*66 + 32 + s];
        dtBs[row*36 + s] = dt * Bv;
    }
    bc += __shfl_xor_sync(0xffffffffu, bc, 1);
    bc += __shfl_xor_sync(0xffffffffu, bc, 2);
    if (part == 0) yav[row] = dt * bc;
}

__global__ void __launch_bounds__(NTHR, 1) fused_kernel(
    const float* __restrict__ x,      const float* __restrict__ w_in,
    const float* __restrict__ b_in,   const float* __restrict__ ln_in_g,
    const float* __restrict__ ln_in_b,
    const float* __restrict__ in_w0,  const float* __restrict__ Dp0,
    const float* __restrict__ out_w0, const float* __restrict__ ln_g0,
    const float* __restrict__ ln_b0,
    const float* __restrict__ in_w1,  const float* __restrict__ Dp1,
    const float* __restrict__ out_w1, const float* __restrict__ ln_g1,
    const float* __restrict__ ln_b1,
    const float* __restrict__ fn_g,   const float* __restrict__ fn_b,
    const float* __restrict__ sh_w1,  const float* __restrict__ sh_b1,
    const float* __restrict__ sh_w2,  const float* __restrict__ sh_b2,
    const float* __restrict__ k_w,    const float* __restrict__ k_b,
    const float* __restrict__ ki_w,   const float* __restrict__ ki_b,
    float* __restrict__ outp)
{
    extern __shared__ float sm[];
    float* hs   = sm + HS_OFF;
    float* xss  = sm + XS_OFF;
    float* ws0  = sm + WS0_OFF;
    float* ws1  = sm + WS1_OFF;
    float* ts   = sm + TS_OFF;
    float* bcs  = sm + BC_OFF;
    float* dtBs = sm + DTB_OFF;
    float* yav  = sm + YA_OFF;

    const int tid  = threadIdx.x;
    const int wid  = tid >> 5, lane = tid & 31;
    const int wr   = wid & 3,  wcc  = wid >> 2;      // warp grid 4x2
    const int lr   = lane >> 3, lc  = lane & 7;      // lane grid 4x8
    const int row0 = wr*16 + lr;                     // rows row0 + 4i
    const int col0 = wcc*32 + lc;                    // cols col0 + 8j
    const int rowbase = blockIdx.x * TB;
    const int r_st = tid >> 3, sq_st = tid & 7;      // state store: rows r_st, r_st+32; quad sq_st

    // ============ input stage: h = LN(x @ w_in^T + b_in) ============
    for (int idx = tid; idx < 64*58; idx += NTHR) {
        int r = idx / 58, k = idx - r*58;
        xss[r*62 + k] = x[(size_t)(rowbase + r)*58 + k];
    }
    for (int idx = tid; idx < 128*58; idx += NTHR) {
        int r = idx / 58, k = idx - r*58;
        ws0[r*62 + k] = w_in[idx];
    }
    __syncthreads();
    #pragma unroll 1
    for (int half = 0; half < 2; half++) {
        ull acc[4][4];
        #pragma unroll
        for (int i = 0; i < 4; i++)
            #pragma unroll
            for (int j = 0; j < 4; j++) acc[i][j] = 0ull;
        #pragma unroll 1
        for (int k = 0; k < 58; k += 2) {
            ull a[4], b[4];
            #pragma unroll
            for (int i = 0; i < 4; i++) a[i] = *(const ull*)(xss + (row0 + 4*i)*62 + k);
            #pragma unroll
            for (int j = 0; j < 4; j++) b[j] = *(const ull*)(ws0 + (half*64 + col0 + 8*j)*62 + k);
            #pragma unroll
            for (int i = 0; i < 4; i++)
                #pragma unroll
                for (int j = 0; j < 4; j++) fma2(acc[i][j], a[i], b[j]);
        }
        #pragma unroll
        for (int i = 0; i < 4; i++)
            #pragma unroll
            for (int j = 0; j < 4; j++) {
                int c = half*64 + col0 + 8*j;
                ts[(row0 + 4*i)*132 + c] = psum(acc[i][j]) + __ldg(b_in + c);
            }
    }
    __syncthreads();
    cpa_slab(ws1, in_w0 + 512*128, 128);           // L0 B|C slab; LN covers latency
    do_ln(hs, ts, 132, ln_in_g, ln_in_b, false);
    cpa_wait();
    __syncthreads();

    float* cur = ws1;
    float* nxt = ws0;

    // ============ two mamba layers ============
    const float* in_w_l[2]  = {in_w0, in_w1};
    const float* Dp_l[2]    = {Dp0, Dp1};
    const float* out_w_l[2] = {out_w0, out_w1};
    const float* g_l[2]     = {ln_g0, ln_g1};
    const float* b_l[2]     = {ln_b0, ln_b1};
    const ull    soff_l[2]  = {ST0_OFF, ST1_OFF};

    for (int L = 0; L < 2; L++) {
        const float* in_w  = in_w_l[L];
        const float* Dp    = Dp_l[L];
        const float* out_w = out_w_l[L];
        const ull    soff  = soff_l[L];
        // state bases: rows r_st and r_st+32, quad sq_st
        float* stbA = outp + soff + (ull)(rowbase + r_st)*8192ull + (ull)(sq_st*4);
        float* stbB = stbA + 32ull*8192ull;
        const float* xrA = xss + r_st*260;
        const float* xrB = xss + (r_st + 32)*260;

        // ---- B|C chunk ----
        {
            cpa_slab(nxt, in_w + 256*128, 128);    // xs0
            float vals[4][4] = {};
            gemm64(hs, 132, cur, vals, row0, col0);
            #pragma unroll
            for (int i = 0; i < 4; i++)
                #pragma unroll
                for (int j = 0; j < 4; j++)
                    bcs[(row0 + 4*i)*66 + col0 + 8*j] = vals[i][j];
            cpa_wait(); __syncthreads();
            { float* t = cur; cur = nxt; nxt = t; }
        }

        // ---- xs chunks (proj cols 256..511) ----
        // carriers (d cursor): xs1:D1@0, xs2:D2@32, xs3:D1@96,
        //                      z0:D2@128, z1:D1@192, z2:D1@224
        for (int sub = 0; sub < 4; sub++) {
            const float* nx = (sub < 3) ? (in_w + (320 + 64*sub)*128) : in_w;  // xs_{sub+1} else z0
            cpa_slab(nxt, nx, 128);
            if (sub == 0) dtdot(hs, bcs, dtBs, yav, in_w + 576*128);
            float vals[4][4] = {};
            if (sub == 0) gemm64(hs, 132, cur, vals, row0, col0);
            else {
                float4 dbA = *(const float4*)(dtBs + r_st*36 + sq_st*4);
                float4 dbB = *(const float4*)(dtBs + (r_st + 32)*36 + sq_st*4);
                if (sub == 1)      gemm64st<1>(hs, 132, cur, vals, row0, col0, xrA, xrB, dbA, dbB, stbA, stbB, 0);
                else if (sub == 2) gemm64st<2>(hs, 132, cur, vals, row0, col0, xrA, xrB, dbA, dbB, stbA, stbB, 32);
                else               gemm64st<1>(hs, 132, cur, vals, row0, col0, xrA, xrB, dbA, dbB, stbA, stbB, 96);
            }
            #pragma unroll
            for (int i = 0; i < 4; i++)
                #pragma unroll
                for (int j = 0; j < 4; j++)
                    xss[(row0 + 4*i)*260 + sub*64 + col0 + 8*j] = siluf(vals[i][j]);
            cpa_wait(); __syncthreads();
            { float* t = cur; cur = nxt; nxt = t; }
        }

        // ---- z chunks (proj cols 0..255) ----
        for (int sub = 0; sub < 4; sub++) {
            if (sub < 3) cpa_slab(nxt, in_w + 64*(sub+1)*128, 128);
            else         cpa_slab(nxt, out_w, 256);                 // o00
            float vals[4][4] = {};
            float4 dbA = *(const float4*)(dtBs + r_st*36 + sq_st*4);
            float4 dbB = *(const float4*)(dtBs + (r_st + 32)*36 + sq_st*4);
            if (sub == 0)      gemm64st<2>(hs, 132, cur, vals, row0, col0, xrA, xrB, dbA, dbB, stbA, stbB, 128);
            else if (sub == 1) gemm64st<1>(hs, 132, cur, vals, row0, col0, xrA, xrB, dbA, dbB, stbA, stbB, 192);
            else if (sub == 2) gemm64st<1>(hs, 132, cur, vals, row0, col0, xrA, xrB, dbA, dbB, stbA, stbB, 224);
            else               gemm64(hs, 132, cur, vals, row0, col0);
            #pragma unroll
            for (int i = 0; i < 4; i++)
                #pragma unroll
                for (int j = 0; j < 4; j++) {
                    int r = row0 + 4*i, c = sub*64 + col0 + 8*j;
                    float xv = xss[r*260 + c];
                    xss[r*260 + c] = siluf(vals[i][j]) * xv * (yav[r] + __ldg(Dp + c));
                }
            cpa_wait(); __syncthreads();
            { float* t = cur; cur = nxt; nxt = t; }
        }

        // ---- out GEMM: ts = u @ out_w^T (128 out cols; 4 slabs) ----
        for (int ch = 0; ch < 2; ch++) {
            float vals[4][4] = {};
            for (int kh = 0; kh < 2; kh++) {
                if (ch == 0 && kh == 0)      cpa_slab(nxt, out_w + 128, 256);
                else if (ch == 0 && kh == 1) cpa_slab(nxt, out_w + 64*256, 256);
                else if (ch == 1 && kh == 0) cpa_slab(nxt, out_w + 64*256 + 128, 256);
                else cpa_slab(nxt, (L == 0) ? (in_w1 + 512*128) : sh_w1, 128);
                gemm64(xss + kh*128, 260, cur, vals, row0, col0);
                if (kh == 1) {
                    #pragma unroll
                    for (int i = 0; i < 4; i++)
                        #pragma unroll
                        for (int j = 0; j < 4; j++)
                            ts[(row0 + 4*i)*132 + ch*64 + col0 + 8*j] = vals[i][j];
                }
                cpa_wait(); __syncthreads();
                { float* t = cur; cur = nxt; nxt = t; }
            }
        }
        do_ln(hs, ts, 132, g_l[L], b_l[L], true);   // h = LN(h + out)
        __syncthreads();
    }

    // ============ final LN + heads ============
    do_ln(hs, hs, 132, fn_g, fn_b, false);
    __syncthreads();

    // t1 = gelu(h @ sh_w1^T + sh_b1) -> bcs; sh_w1 is in cur
    {
        float vals[4][4] = {};
        gemm64(hs, 132, cur, vals, row0, col0);
        #pragma unroll
        for (int i = 0; i < 4; i++)
            #pragma unroll
            for (int j = 0; j < 4; j++) {
                int c = col0 + 8*j;
                bcs[(row0 + 4*i)*66 + c] = geluf(vals[i][j] + __ldg(sh_b1 + c));
            }
    }
    __syncthreads();

    // scaling = softplus(t1 @ sh_w2^T + sh_b2)  (9 cols)
    for (int idx = tid; idx < 64*9; idx += NTHR) {
        int r = idx / 9, c = idx - r*9;
        float acc = __ldg(sh_b2 + c);
        #pragma unroll 4
        for (int ss = 0; ss < 64; ss++) {
            int s = (ss + tid) & 63;
            acc += bcs[r*66 + s] * __ldg(sh_w2 + c*64 + s);
        }
        outp[SCAL_OFF + (ull)(rowbase + r)*9ull + c] = softpl(acc);
    }

    // K, K_internal (per-row dots over h)
    if (tid < 64) {
        float a0 = 0.f, a1 = 0.f;
        #pragma unroll 4
        for (int kk = 0; kk < 128; kk++) {
            int k = (kk + tid) & 127;
            float hv = hs[tid*132 + k];
            a0 += hv * __ldg(k_w + k);
            a1 += hv * __ldg(ki_w + k);
        }
        outp[K_OFF  + (ull)(rowbase + tid)] = sigm(a0 + __ldg(k_b));
        outp[KI_OFF + (ull)(rowbase + tid)] = sigm(a1 + __ldg(ki_b));
    }
}

extern "C" void kernel_launch(void* const* d_in, const int* in_sizes, int n_in,
                              void* d_out, int out_size) {
    (void)in_sizes; (void)n_in; (void)out_size;
    cudaFuncSetAttribute(fused_kernel, cudaFuncAttributeMaxDynamicSharedMemorySize, SMEM_BYTES);
    fused_kernel<<<NBLK, NTHR, SMEM_BYTES>>>(
        (const float*)d_in[0],  (const float*)d_in[1],  (const float*)d_in[2],
        (const float*)d_in[3],  (const float*)d_in[4],
        (const float*)d_in[5],  (const float*)d_in[7],  (const float*)d_in[8],
        (const float*)d_in[9],  (const float*)d_in[10],
        (const float*)d_in[11], (const float*)d_in[13], (const float*)d_in[14],
        (const float*)d_in[15], (const float*)d_in[16],
        (const float*)d_in[17], (const float*)d_in[18],
        (const float*)d_in[19], (const float*)d_in[20],
        (const float*)d_in[21], (const float*)d_in[22],
        (const float*)d_in[23], (const float*)d_in[24],
        (const float*)d_in[25], (const float*)d_in[26],
        (float*)d_out);
}